// round 7
// baseline (speedup 1.0000x reference)
#include <cuda_runtime.h>
#include <cstdint>

#define NN 100000
#define NE 1600000
#define NG 512
#define FD 100
#define FD2 200
#define OUTSZ (NG*2 + NG*200)

// ---------------- scratch (device globals; no allocation allowed) ----------------
__device__ float g_m [NN*FD];    // conv1 message values relu(lin_src(x))+eps
__device__ float g_xd[NN*FD];    // conv1 lin_dst(x)
__device__ float g_out[NN*FD];   // agg + x_dst  (MLP input)
__device__ float g_hh[NN*FD2];   // MLP hidden
__device__ float g_h [NN*FD];    // node features between convs (post-ReLU)
__device__ int   g_src[NE];
__device__ int   g_dst[NE];
__device__ int   g_col[NE];      // CSR column (source node) per dst-sorted slot
__device__ int   g_rowptr[NN+1];
__device__ int   g_cursor[NN];
__device__ int   g_counts[NN];
__device__ int   g_batch[NN];
__device__ int   g_bsums[128];
__device__ int   g_boffs[128];
__device__ int   g_gcnt[NG];
__device__ float    g_rosum[NG*FD];
__device__ unsigned g_romax[NG*FD];
__device__ int   g_is64;

// ---------------- dtype sniff: int64 vs int32 index storage ----------------
__global__ void detect_kernel(const unsigned long long* __restrict__ ei) {
    __shared__ int found;
    if (threadIdx.x == 0) found = 0;
    __syncthreads();
    unsigned long long v = ei[threadIdx.x];   // 8KB probe, safe under either dtype
    if ((v >> 32) != 0ULL) found = 1;         // benign race
    __syncthreads();
    if (threadIdx.x == 0) g_is64 = found ? 0 : 1;
}

// ---------------- prep: convert indices, zero counters + output ----------------
__global__ void prep_kernel(const void* __restrict__ ei, const void* __restrict__ bt,
                            float* __restrict__ out) {
    int i = blockIdx.x * blockDim.x + threadIdx.x;
    int is64 = g_is64;
    if (i < NE) {
        if (is64) {
            const long long* e = (const long long*)ei;
            g_src[i] = (int)e[i];
            g_dst[i] = (int)e[NE + i];
        } else {
            const int* e = (const int*)ei;
            g_src[i] = e[i];
            g_dst[i] = e[NE + i];
        }
    }
    if (i < NN) {
        if (is64) g_batch[i] = (int)((const long long*)bt)[i];
        else      g_batch[i] = ((const int*)bt)[i];
        g_counts[i] = 0;
    }
    if (i < NG)    g_gcnt[i] = 0;
    if (i < OUTSZ) out[i] = 0.0f;
}

__global__ void hist_kernel() {
    int i = blockIdx.x * blockDim.x + threadIdx.x;
    if (i < NE) atomicAdd(&g_counts[g_dst[i]], 1);
    if (i < NN) atomicAdd(&g_gcnt[g_batch[i]], 1);
}

// ---------------- 3-step exclusive scan over counts ----------------
__global__ void scan_block_kernel() {
    __shared__ int sh[1024];
    int t = threadIdx.x;
    int i = blockIdx.x * 1024 + t;
    int v = (i < NN) ? g_counts[i] : 0;
    sh[t] = v;
    __syncthreads();
    for (int off = 1; off < 1024; off <<= 1) {
        int tmp = (t >= off) ? sh[t - off] : 0;
        __syncthreads();
        sh[t] += tmp;
        __syncthreads();
    }
    if (i < NN) g_rowptr[i] = sh[t] - v;          // block-local exclusive
    if (t == 1023) g_bsums[blockIdx.x] = sh[1023];
}

__global__ void scan_bsums_kernel(int nb) {
    if (threadIdx.x == 0) {
        int run = 0;
        for (int i = 0; i < nb; i++) { g_boffs[i] = run; run += g_bsums[i]; }
        g_rowptr[NN] = run;
    }
}

__global__ void scan_add_kernel() {
    int i = blockIdx.x * blockDim.x + threadIdx.x;
    if (i < NN) {
        int r = g_rowptr[i] + g_boffs[i >> 10];
        g_rowptr[i] = r;
        g_cursor[i] = r;
    }
}

__global__ void scatter_kernel() {
    int i = blockIdx.x * blockDim.x + threadIdx.x;
    if (i < NE) {
        int p = atomicAdd(&g_cursor[g_dst[i]], 1);
        g_col[p] = g_src[i];
    }
}

// ---------------- conv1 input linears: m = relu(x@Wsrc^T+bs)+eps, xd = x@Wdst^T+bd ----------------
__global__ void lin10_kernel(const float* __restrict__ x,
                             const float* __restrict__ sw_, const float* __restrict__ sb_,
                             const float* __restrict__ dw_, const float* __restrict__ db_,
                             float* __restrict__ m_out, float* __restrict__ xd_out) {
    __shared__ float sw[1000], dw[1000], sb[100], db[100];
    int t = threadIdx.x;
    for (int i = t; i < 1000; i += blockDim.x) { sw[i] = sw_[i]; dw[i] = dw_[i]; }
    for (int i = t; i < 100;  i += blockDim.x) { sb[i] = sb_[i]; db[i] = db_[i]; }
    __syncthreads();
    int id = blockIdx.x * blockDim.x + t;
    if (id >= NN * FD) return;
    int n = id / FD, f = id - n * FD;
    float xs[10];
#pragma unroll
    for (int k = 0; k < 10; k++) xs[k] = x[n * 10 + k];
    float a = sb[f], b = db[f];
#pragma unroll
    for (int k = 0; k < 10; k++) { a += xs[k] * sw[f * 10 + k]; b += xs[k] * dw[f * 10 + k]; }
    m_out[id]  = fmaxf(a, 0.0f) + 1e-7f;
    xd_out[id] = b;
}

// ---------------- softmax aggregation: warp per destination node, two-pass, no atomics ----------------
// TRANS: apply relu(.)+1e-7 to gathered values (conv2/3 where m comes straight from h)
template<bool TRANS>
__global__ void agg_kernel(const float* __restrict__ m, const float* __restrict__ xd,
                           float* __restrict__ out) {
    int w = (blockIdx.x * blockDim.x + threadIdx.x) >> 5;
    if (w >= NN) return;
    int lane = threadIdx.x & 31;
    int beg = g_rowptr[w], end = g_rowptr[w + 1];

    float mx0 = 0.f, mx1 = 0.f, mx2 = 0.f, mx3 = 0.f;
    for (int i = beg; i < end; i++) {
        int s = __ldg(&g_col[i]);
        const float* r = m + (size_t)s * FD;
        float v0 = r[lane], v1 = r[lane + 32], v2 = r[lane + 64];
        float v3 = 0.f;
        if (lane < 4) v3 = r[lane + 96];
        if (TRANS) {
            v0 = fmaxf(v0, 0.f) + 1e-7f; v1 = fmaxf(v1, 0.f) + 1e-7f;
            v2 = fmaxf(v2, 0.f) + 1e-7f; v3 = fmaxf(v3, 0.f) + 1e-7f;
        }
        mx0 = fmaxf(mx0, v0); mx1 = fmaxf(mx1, v1);
        mx2 = fmaxf(mx2, v2); mx3 = fmaxf(mx3, v3);
    }
    float d0 = 0.f, d1 = 0.f, d2 = 0.f, d3 = 0.f;
    float n0 = 0.f, n1 = 0.f, n2 = 0.f, n3 = 0.f;
    for (int i = beg; i < end; i++) {
        int s = __ldg(&g_col[i]);
        const float* r = m + (size_t)s * FD;
        float v0 = r[lane], v1 = r[lane + 32], v2 = r[lane + 64];
        float v3 = 0.f;
        if (lane < 4) v3 = r[lane + 96];
        if (TRANS) {
            v0 = fmaxf(v0, 0.f) + 1e-7f; v1 = fmaxf(v1, 0.f) + 1e-7f;
            v2 = fmaxf(v2, 0.f) + 1e-7f; v3 = fmaxf(v3, 0.f) + 1e-7f;
        }
        float e0 = __expf(v0 - mx0), e1 = __expf(v1 - mx1);
        float e2 = __expf(v2 - mx2), e3 = __expf(v3 - mx3);
        d0 += e0; d1 += e1; d2 += e2; d3 += e3;
        n0 += e0 * v0; n1 += e1 * v1; n2 += e2 * v2; n3 += e3 * v3;
    }
    size_t o = (size_t)w * FD;
    out[o + lane]      = n0 / (d0 + 1e-16f) + xd[o + lane];
    out[o + lane + 32] = n1 / (d1 + 1e-16f) + xd[o + lane + 32];
    out[o + lane + 64] = n2 / (d2 + 1e-16f) + xd[o + lane + 64];
    if (lane < 4)
        out[o + lane + 96] = n3 / (d3 + 1e-16f) + xd[o + lane + 96];
}

// ---------------- register-tiled fp32 GEMM: C = A[M,K] @ W[NOUT,K]^T, fused epilogue ----------------
// grid: (ceil(M/64), NOUT/100). Block 256 threads; threads<200 compute 8 rows x 4 cols.
// EPI 0: y = relu((acc+bias)*gamma/sqrt(1+1e-5)+beta)   EPI 1: y = relu(acc+bias)
template<int EPI>
__global__ __launch_bounds__(256) void gemm_kernel(
    const float* __restrict__ A, const float* __restrict__ W,
    const float* __restrict__ bias, const float* __restrict__ gamma,
    const float* __restrict__ beta, float* __restrict__ C,
    int M, int K, int NOUT) {
    __shared__ __align__(16) float AsT[50][68];  // [k][row] (transposed, padded)
    __shared__ __align__(16) float Ws [50][100]; // [k][col]
    const int tid  = threadIdx.x;
    const int row0 = blockIdx.x * 64;
    const int j0   = blockIdx.y * 100;
    const int tx = tid % 25;   // col group: cols j0 + 4*tx .. +3
    const int ty = tid / 25;   // row group: rows row0 + 8*ty .. +7 (valid for tid<200)

    float acc[8][4];
#pragma unroll
    for (int i = 0; i < 8; i++)
#pragma unroll
        for (int j = 0; j < 4; j++) acc[i][j] = 0.f;

    for (int kk = 0; kk < K; kk += 50) {
        // load A tile (coalesced over k within each row), transpose into smem
        for (int i = tid; i < 64 * 50; i += 256) {
            int r = i / 50, k = i - r * 50;
            int gr = row0 + r;
            AsT[k][r] = (gr < M) ? A[(size_t)gr * K + kk + k] : 0.f;
        }
        // load W panel (coalesced over k within each output row)
        for (int i = tid; i < 100 * 50; i += 256) {
            int j = i / 50, k = i - j * 50;
            Ws[k][j] = W[(size_t)(j0 + j) * K + kk + k];
        }
        __syncthreads();
        if (tid < 200) {
#pragma unroll 2
            for (int k = 0; k < 50; k++) {
                float bv[4], av[8];
                *(float4*)&bv[0] = *(const float4*)&Ws[k][tx * 4];
                *(float4*)&av[0] = *(const float4*)&AsT[k][ty * 8];
                *(float4*)&av[4] = *(const float4*)&AsT[k][ty * 8 + 4];
#pragma unroll
                for (int i = 0; i < 8; i++)
#pragma unroll
                    for (int j = 0; j < 4; j++)
                        acc[i][j] += av[i] * bv[j];
            }
        }
        __syncthreads();
    }

    if (tid < 200) {
        int c0 = j0 + tx * 4;
        float bb[4], sc[4], be[4];
#pragma unroll
        for (int j = 0; j < 4; j++) {
            bb[j] = bias[c0 + j];
            if (EPI == 0) {
                const float rs = rsqrtf(1.0f + 1e-5f);
                sc[j] = gamma[c0 + j] * rs;
                be[j] = beta[c0 + j];
            }
        }
#pragma unroll
        for (int i = 0; i < 8; i++) {
            int gr = row0 + ty * 8 + i;
            if (gr < M) {
                float4 y;
                float v[4];
#pragma unroll
                for (int j = 0; j < 4; j++) {
                    float t = acc[i][j] + bb[j];
                    if (EPI == 0) t = t * sc[j] + be[j];
                    v[j] = fmaxf(t, 0.f);
                }
                y.x = v[0]; y.y = v[1]; y.z = v[2]; y.w = v[3];
                *(float4*)&C[(size_t)gr * NOUT + c0] = y;
            }
        }
    }
}

// ---------------- readout ----------------
__global__ void ro_init_kernel() {
    int i = blockIdx.x * blockDim.x + threadIdx.x;
    if (i < NG * FD) { g_rosum[i] = 0.f; g_romax[i] = 0u; }
}

__global__ void readout_acc_kernel(const float* __restrict__ h) {
    int t = blockIdx.x * blockDim.x + threadIdx.x;
    if (t >= NN * FD) return;
    int n = t / FD, f = t - n * FD;
    float v = h[t];                       // h >= 0 (post-ReLU)
    int g = g_batch[n];
    atomicAdd(&g_rosum[g * FD + f], v);
    atomicMax(&g_romax[g * FD + f], __float_as_uint(v));
}

__global__ void readout_fin_kernel(float* __restrict__ encode) {
    int t = blockIdx.x * blockDim.x + threadIdx.x;
    if (t >= NG * FD) return;
    int g = t / FD, f = t - g * FD;
    float cnt  = (float)g_gcnt[g];
    float mean = g_rosum[t] / fmaxf(cnt, 1.0f);
    float mx   = __uint_as_float(g_romax[t]);
    encode[g * FD2 + f]      += fmaxf(mean, 0.f);
    encode[g * FD2 + FD + f] += fmaxf(mx,   0.f);
}

// ---------------- head: z = relu(encode@fc1^T+b); logits = z@cls^T+b ----------------
__global__ void head_kernel(const float* __restrict__ encode,
                            const float* __restrict__ fc1_w, const float* __restrict__ fc1_b,
                            const float* __restrict__ cls_w, const float* __restrict__ cls_b,
                            float* __restrict__ logits) {
    __shared__ float enc[200];
    __shared__ float z[100];
    int g = blockIdx.x, t = threadIdx.x;
    for (int i = t; i < 200; i += 128) enc[i] = encode[g * 200 + i];
    __syncthreads();
    if (t < 100) {
        float a = fc1_b[t];
#pragma unroll 4
        for (int k = 0; k < 200; k++) a += enc[k] * __ldg(&fc1_w[t * 200 + k]);
        z[t] = fmaxf(a, 0.f);
    }
    __syncthreads();
    if (t < 64) {
        int o = t >> 5, lane = t & 31;
        float s = 0.f;
        for (int j = lane; j < 100; j += 32) s += z[j] * __ldg(&cls_w[o * 100 + j]);
#pragma unroll
        for (int off = 16; off; off >>= 1) s += __shfl_down_sync(0xffffffffu, s, off);
        if (lane == 0) logits[g * 2 + o] = s + cls_b[o];
    }
}

// ---------------- launch ----------------
extern "C" void kernel_launch(void* const* d_in, const int* in_sizes, int n_in,
                              void* d_out, int out_size) {
    const float* x       = (const float*)d_in[0];
    const void*  ei      = d_in[1];
    const void*  bt      = d_in[2];
    const float* c1_src_w = (const float*)d_in[3];
    const float* c1_src_b = (const float*)d_in[4];
    const float* c1_dst_w = (const float*)d_in[5];
    const float* c1_dst_b = (const float*)d_in[6];
    const float* cw1[3] = { (const float*)d_in[7],  (const float*)d_in[13], (const float*)d_in[19] };
    const float* cb1[3] = { (const float*)d_in[8],  (const float*)d_in[14], (const float*)d_in[20] };
    const float* cg [3] = { (const float*)d_in[9],  (const float*)d_in[15], (const float*)d_in[21] };
    const float* cbe[3] = { (const float*)d_in[10], (const float*)d_in[16], (const float*)d_in[22] };
    const float* cw2[3] = { (const float*)d_in[11], (const float*)d_in[17], (const float*)d_in[23] };
    const float* cb2[3] = { (const float*)d_in[12], (const float*)d_in[18], (const float*)d_in[24] };
    const float* fc1_w = (const float*)d_in[25];
    const float* fc1_b = (const float*)d_in[26];
    const float* cls_w = (const float*)d_in[27];
    const float* cls_b = (const float*)d_in[28];

    float* out    = (float*)d_out;
    float* logits = out;
    float* encode = out + NG * 2;

    float *pm, *pxd, *pout, *phh, *ph;
    cudaGetSymbolAddress((void**)&pm,   g_m);
    cudaGetSymbolAddress((void**)&pxd,  g_xd);
    cudaGetSymbolAddress((void**)&pout, g_out);
    cudaGetSymbolAddress((void**)&phh,  g_hh);
    cudaGetSymbolAddress((void**)&ph,   g_h);

    const int TB = 256;
    const int GE = (NE + TB - 1) / TB;
    const int GNF = (NN * FD + TB - 1) / TB;
    const int GGF = (NG * FD + TB - 1) / TB;
    const int NB_SCAN = (NN + 1023) / 1024;
    dim3 gg1((NN + 63) / 64, 2);
    dim3 gg2((NN + 63) / 64, 1);

    // CSR build (dst is identical across all 3 convs -> build once)
    detect_kernel<<<1, 1024>>>((const unsigned long long*)ei);
    prep_kernel<<<GE, TB>>>(ei, bt, out);
    hist_kernel<<<GE, TB>>>();
    scan_block_kernel<<<NB_SCAN, 1024>>>();
    scan_bsums_kernel<<<1, 32>>>(NB_SCAN);
    scan_add_kernel<<<(NN + TB - 1) / TB, TB>>>();
    scatter_kernel<<<GE, TB>>>();

    // ---- conv1 ----
    lin10_kernel<<<GNF, TB>>>(x, c1_src_w, c1_src_b, c1_dst_w, c1_dst_b, pm, pxd);
    agg_kernel<false><<<(NN * 32 + TB - 1) / TB, TB>>>(pm, pxd, pout);
    gemm_kernel<0><<<gg1, 256>>>(pout, cw1[0], cb1[0], cg[0], cbe[0], phh, NN, 100, 200);
    gemm_kernel<1><<<gg2, 256>>>(phh, cw2[0], cb2[0], nullptr, nullptr, ph, NN, 200, 100);
    ro_init_kernel<<<GGF, TB>>>();
    readout_acc_kernel<<<GNF, TB>>>(ph);
    readout_fin_kernel<<<GGF, TB>>>(encode);

    // ---- conv2 / conv3 ----
    for (int c = 1; c < 3; c++) {
        agg_kernel<true><<<(NN * 32 + TB - 1) / TB, TB>>>(ph, ph, pout);
        gemm_kernel<0><<<gg1, 256>>>(pout, cw1[c], cb1[c], cg[c], cbe[c], phh, NN, 100, 200);
        gemm_kernel<1><<<gg2, 256>>>(phh, cw2[c], cb2[c], nullptr, nullptr, ph, NN, 200, 100);
        ro_init_kernel<<<GGF, TB>>>();
        readout_acc_kernel<<<GNF, TB>>>(ph);
        readout_fin_kernel<<<GGF, TB>>>(encode);
    }

    head_kernel<<<NG, 128>>>(encode, fc1_w, fc1_b, cls_w, cls_b, logits);
}

// round 9
// speedup vs baseline: 1.2244x; 1.2244x over previous
#include <cuda_runtime.h>
#include <cuda_bf16.h>
#include <cstdint>

#define NN 100000
#define NE 1600000
#define NG 512
#define FD 100
#define FD2 200
#define OUTSZ (NG*2 + NG*200)

#define KP1 112   // GEMM1 K padded (100 -> 112)
#define NC1 208   // GEMM1 N covered (200 -> 208)
#define KP2 208   // GEMM2 K padded (200 -> 208)
#define NC2 112   // GEMM2 N covered (100 -> 112)

// ---------------- scratch (device globals; no allocation allowed) ----------------
__device__ float g_m [NN*FD];
__device__ float g_xd[NN*FD];
__device__ float g_out[NN*FD];
__device__ float g_h [NN*FD];
__device__ int   g_src[NE];
__device__ int   g_dst[NE];
__device__ int   g_col[NE];
__device__ int   g_rowptr[NN+1];
__device__ int   g_cursor[NN];
__device__ int   g_counts[NN];
__device__ int   g_batch[NN];
__device__ int   g_bsums[128];
__device__ int   g_boffs[128];
__device__ int   g_gcnt[NG];
__device__ float    g_rosum[NG*FD];
__device__ unsigned g_romax[NG*FD];
__device__ int   g_is64;

// bf16 hi/lo split operands for tensor-core GEMMs
__device__ __nv_bfloat16 g_a1h[NN*KP1], g_a1l[NN*KP1];        // GEMM1 input  [NN,112]
__device__ __nv_bfloat16 g_a2h[NN*KP2], g_a2l[NN*KP2];        // GEMM2 input  [NN,208]
__device__ __nv_bfloat16 g_w1h[3*NC1*KP1], g_w1l[3*NC1*KP1];  // W1 [208,112]
__device__ __nv_bfloat16 g_w2h[3*NC2*KP2], g_w2l[3*NC2*KP2];  // W2 [112,208]

// ================= mma.sync helpers (baseline PTX, sm_80+) =================
__device__ __forceinline__ uint32_t smem_u32(const void* p) {
    uint32_t a;
    asm("{ .reg .u64 t; cvta.to.shared.u64 t, %1; cvt.u32.u64 %0, t; }" : "=r"(a) : "l"(p));
    return a;
}
__device__ __forceinline__ void ldmx4(uint32_t* a, uint32_t addr) {
    asm volatile("ldmatrix.sync.aligned.m8n8.x4.shared.b16 {%0,%1,%2,%3}, [%4];"
        : "=r"(a[0]), "=r"(a[1]), "=r"(a[2]), "=r"(a[3]) : "r"(addr));
}
__device__ __forceinline__ void ldmx2(uint32_t* b, uint32_t addr) {
    asm volatile("ldmatrix.sync.aligned.m8n8.x2.shared.b16 {%0,%1}, [%2];"
        : "=r"(b[0]), "=r"(b[1]) : "r"(addr));
}
__device__ __forceinline__ void mma16816(float* d, const uint32_t* a, const uint32_t* b) {
    asm volatile("mma.sync.aligned.m16n8k16.row.col.f32.bf16.bf16.f32 "
        "{%0,%1,%2,%3}, {%4,%5,%6,%7}, {%8,%9}, {%0,%1,%2,%3};"
        : "+f"(d[0]), "+f"(d[1]), "+f"(d[2]), "+f"(d[3])
        : "r"(a[0]), "r"(a[1]), "r"(a[2]), "r"(a[3]), "r"(b[0]), "r"(b[1]));
}
__device__ __forceinline__ uint32_t pack_bf2(float a, float b) {
    __nv_bfloat162 t = __floats2bfloat162_rn(a, b);
    return reinterpret_cast<uint32_t&>(t);
}

// ---------------- dtype sniff ----------------
__global__ void detect_kernel(const unsigned long long* __restrict__ ei) {
    __shared__ int found;
    if (threadIdx.x == 0) found = 0;
    __syncthreads();
    unsigned long long v = ei[threadIdx.x];
    if ((v >> 32) != 0ULL) found = 1;
    __syncthreads();
    if (threadIdx.x == 0) g_is64 = found ? 0 : 1;
}

__global__ void prep_kernel(const void* __restrict__ ei, const void* __restrict__ bt,
                            float* __restrict__ out) {
    int i = blockIdx.x * blockDim.x + threadIdx.x;
    int is64 = g_is64;
    if (i < NE) {
        if (is64) {
            const long long* e = (const long long*)ei;
            g_src[i] = (int)e[i];
            g_dst[i] = (int)e[NE + i];
        } else {
            const int* e = (const int*)ei;
            g_src[i] = e[i];
            g_dst[i] = e[NE + i];
        }
    }
    if (i < NN) {
        if (is64) g_batch[i] = (int)((const long long*)bt)[i];
        else      g_batch[i] = ((const int*)bt)[i];
        g_counts[i] = 0;
    }
    if (i < NG)    g_gcnt[i] = 0;
    if (i < OUTSZ) out[i] = 0.0f;
}

__global__ void hist_kernel() {
    int i = blockIdx.x * blockDim.x + threadIdx.x;
    if (i < NE) atomicAdd(&g_counts[g_dst[i]], 1);
    if (i < NN) atomicAdd(&g_gcnt[g_batch[i]], 1);
}

__global__ void scan_block_kernel() {
    __shared__ int sh[1024];
    int t = threadIdx.x;
    int i = blockIdx.x * 1024 + t;
    int v = (i < NN) ? g_counts[i] : 0;
    sh[t] = v;
    __syncthreads();
    for (int off = 1; off < 1024; off <<= 1) {
        int tmp = (t >= off) ? sh[t - off] : 0;
        __syncthreads();
        sh[t] += tmp;
        __syncthreads();
    }
    if (i < NN) g_rowptr[i] = sh[t] - v;
    if (t == 1023) g_bsums[blockIdx.x] = sh[1023];
}

__global__ void scan_bsums_kernel(int nb) {
    if (threadIdx.x == 0) {
        int run = 0;
        for (int i = 0; i < nb; i++) { g_boffs[i] = run; run += g_bsums[i]; }
        g_rowptr[NN] = run;
    }
}

__global__ void scan_add_kernel() {
    int i = blockIdx.x * blockDim.x + threadIdx.x;
    if (i < NN) {
        int r = g_rowptr[i] + g_boffs[i >> 10];
        g_rowptr[i] = r;
        g_cursor[i] = r;
    }
}

__global__ void scatter_kernel() {
    int i = blockIdx.x * blockDim.x + threadIdx.x;
    if (i < NE) {
        int p = atomicAdd(&g_cursor[g_dst[i]], 1);
        g_col[p] = g_src[i];
    }
}

// ---------------- conv1 input linears ----------------
__global__ void lin10_kernel(const float* __restrict__ x,
                             const float* __restrict__ sw_, const float* __restrict__ sb_,
                             const float* __restrict__ dw_, const float* __restrict__ db_,
                             float* __restrict__ m_out, float* __restrict__ xd_out) {
    __shared__ float sw[1000], dw[1000], sb[100], db[100];
    int t = threadIdx.x;
    for (int i = t; i < 1000; i += blockDim.x) { sw[i] = sw_[i]; dw[i] = dw_[i]; }
    for (int i = t; i < 100;  i += blockDim.x) { sb[i] = sb_[i]; db[i] = db_[i]; }
    __syncthreads();
    int id = blockIdx.x * blockDim.x + t;
    if (id >= NN * FD) return;
    int n = id / FD, f = id - n * FD;
    float xs[10];
#pragma unroll
    for (int k = 0; k < 10; k++) xs[k] = x[n * 10 + k];
    float a = sb[f], b = db[f];
#pragma unroll
    for (int k = 0; k < 10; k++) { a += xs[k] * sw[f * 10 + k]; b += xs[k] * dw[f * 10 + k]; }
    m_out[id]  = fmaxf(a, 0.0f) + 1e-7f;
    xd_out[id] = b;
}

// ---------------- softmax aggregation (warp per dst node) ----------------
template<bool TRANS>
__global__ void agg_kernel(const float* __restrict__ m, const float* __restrict__ xd,
                           float* __restrict__ out) {
    int w = (blockIdx.x * blockDim.x + threadIdx.x) >> 5;
    if (w >= NN) return;
    int lane = threadIdx.x & 31;
    int beg = g_rowptr[w], end = g_rowptr[w + 1];

    float mx0 = 0.f, mx1 = 0.f, mx2 = 0.f, mx3 = 0.f;
    for (int i = beg; i < end; i++) {
        int s = __ldg(&g_col[i]);
        const float* r = m + (size_t)s * FD;
        float v0 = r[lane], v1 = r[lane + 32], v2 = r[lane + 64];
        float v3 = 0.f;
        if (lane < 4) v3 = r[lane + 96];
        if (TRANS) {
            v0 = fmaxf(v0, 0.f) + 1e-7f; v1 = fmaxf(v1, 0.f) + 1e-7f;
            v2 = fmaxf(v2, 0.f) + 1e-7f; v3 = fmaxf(v3, 0.f) + 1e-7f;
        }
        mx0 = fmaxf(mx0, v0); mx1 = fmaxf(mx1, v1);
        mx2 = fmaxf(mx2, v2); mx3 = fmaxf(mx3, v3);
    }
    float d0 = 0.f, d1 = 0.f, d2 = 0.f, d3 = 0.f;
    float n0 = 0.f, n1 = 0.f, n2 = 0.f, n3 = 0.f;
    for (int i = beg; i < end; i++) {
        int s = __ldg(&g_col[i]);
        const float* r = m + (size_t)s * FD;
        float v0 = r[lane], v1 = r[lane + 32], v2 = r[lane + 64];
        float v3 = 0.f;
        if (lane < 4) v3 = r[lane + 96];
        if (TRANS) {
            v0 = fmaxf(v0, 0.f) + 1e-7f; v1 = fmaxf(v1, 0.f) + 1e-7f;
            v2 = fmaxf(v2, 0.f) + 1e-7f; v3 = fmaxf(v3, 0.f) + 1e-7f;
        }
        float e0 = __expf(v0 - mx0), e1 = __expf(v1 - mx1);
        float e2 = __expf(v2 - mx2), e3 = __expf(v3 - mx3);
        d0 += e0; d1 += e1; d2 += e2; d3 += e3;
        n0 += e0 * v0; n1 += e1 * v1; n2 += e2 * v2; n3 += e3 * v3;
    }
    size_t o = (size_t)w * FD;
    out[o + lane]      = n0 / (d0 + 1e-16f) + xd[o + lane];
    out[o + lane + 32] = n1 / (d1 + 1e-16f) + xd[o + lane + 32];
    out[o + lane + 64] = n2 / (d2 + 1e-16f) + xd[o + lane + 64];
    if (lane < 4)
        out[o + lane + 96] = n3 / (d3 + 1e-16f) + xd[o + lane + 96];
}

// ---------------- hi/lo bf16 split kernels ----------------
__global__ void split_a_kernel(const float* __restrict__ in,
                               __nv_bfloat16* __restrict__ oh, __nv_bfloat16* __restrict__ ol) {
    int i = blockIdx.x * blockDim.x + threadIdx.x;
    if (i >= NN * KP1) return;
    int n = i / KP1, f = i - n * KP1;
    float v = (f < FD) ? in[n * FD + f] : 0.f;
    __nv_bfloat16 h = __float2bfloat16(v);
    oh[i] = h;
    ol[i] = __float2bfloat16(v - __bfloat162float(h));
}

__global__ void prep_w_kernel(const float* __restrict__ w,
                              __nv_bfloat16* __restrict__ oh, __nv_bfloat16* __restrict__ ol,
                              int R, int K, int Kp, int total) {
    int i = blockIdx.x * blockDim.x + threadIdx.x;
    if (i >= total) return;
    int r = i / Kp, k = i - r * Kp;
    float v = (r < R && k < K) ? w[r * K + k] : 0.f;
    __nv_bfloat16 h = __float2bfloat16(v);
    oh[i] = h;
    ol[i] = __float2bfloat16(v - __bfloat162float(h));
}

// ============ persistent mma.sync bf16 GEMM: C[M, NCOV] = A @ W^T ============
// A: [NN, KPAD] bf16 hi/lo. W: [NCOV, KPAD] bf16 hi/lo (zero padded).
// 3 error-compensated passes: AhWh + AhWl + AlWh, fp32 accumulate.
// SMS = smem row stride in elements, chosen SMS % 64 == 56 -> conflict-free ldmatrix.
// EPI 0: v = relu((acc+bias)*gamma*rsqrt(1+1e-5)+beta) -> bf16 hi/lo Oh/Ol [NN,NCOV] (0 for c>=NOUT)
// EPI 1: v = relu(acc+bias) -> fp32 Of [NN,100] (cols >= NOUT skipped)
template<int NOUT, int NCOV, int KPAD, int SMS, int MT, int MF, int NF, int WARPS_M, int EPI>
__global__ __launch_bounds__(256, 1) void mma_gemm_kernel(
    const __nv_bfloat16* __restrict__ Ah, const __nv_bfloat16* __restrict__ Al,
    const __nv_bfloat16* __restrict__ Wh, const __nv_bfloat16* __restrict__ Wl,
    const float* __restrict__ bias, const float* __restrict__ gamma, const float* __restrict__ beta,
    __nv_bfloat16* __restrict__ Oh, __nv_bfloat16* __restrict__ Ol, float* __restrict__ Of) {

    constexpr int WM = MF * 16;
    constexpr int WN = NF * 8;
    constexpr int KC = KPAD / 8;     // uint4 chunks per row
    constexpr int KS = KPAD / 16;    // k-steps
    constexpr int POFF = (3 * NCOV * 4 + 15) & ~15;

    extern __shared__ char sm[];
    float* p_b = (float*)sm;
    float* p_s = p_b + NCOV;
    float* p_e = p_s + NCOV;
    __nv_bfloat16* sAh = (__nv_bfloat16*)(sm + POFF);
    __nv_bfloat16* sAl = sAh + MT * SMS;
    __nv_bfloat16* sWh = sAl + MT * SMS;
    __nv_bfloat16* sWl = sWh + NCOV * SMS;

    const int tid = threadIdx.x, wid = tid >> 5, lane = tid & 31;
    const int wm = wid % WARPS_M, wn = wid / WARPS_M;

    // epilogue params
    const float rs = rsqrtf(1.0f + 1e-5f);
    for (int i = tid; i < NCOV; i += 256) {
        p_b[i] = (i < NOUT) ? bias[i] : 0.f;
        if (EPI == 0) {
            p_s[i] = (i < NOUT) ? gamma[i] * rs : 0.f;
            p_e[i] = (i < NOUT) ? beta[i] : 0.f;
        }
    }
    // weight panel -> smem (hi + lo)
    for (int u = tid; u < NCOV * KC; u += 256) {
        int r = u / KC, k8 = u - r * KC;
        size_t gi = (size_t)r * KPAD + k8 * 8;
        *(uint4*)(sWh + r * SMS + k8 * 8) = *(const uint4*)(Wh + gi);
        *(uint4*)(sWl + r * SMS + k8 * 8) = *(const uint4*)(Wl + gi);
    }
    __syncthreads();

    const uint32_t uAh = smem_u32(sAh), uAl = smem_u32(sAl);
    const uint32_t uWh = smem_u32(sWh), uWl = smem_u32(sWl);
    // ldmatrix lane-address components
    const int a_row  = wm * WM + (lane & 15);
    const int a_koff = (lane >> 4) * 8;
    const int b_row  = wn * WN + (lane & 7);
    const int b_koff = ((lane >> 3) & 1) * 8;

    const int NT = (NN + MT - 1) / MT;
    for (int tile = blockIdx.x; tile < NT; tile += gridDim.x) {
        const int row0 = tile * MT;
        // stage A tile (hi + lo), zero-fill rows >= NN
        for (int u = tid; u < MT * KC; u += 256) {
            int r = u / KC, k8 = u - r * KC;
            int gr = row0 + r;
            uint4 vh = make_uint4(0, 0, 0, 0), vl = make_uint4(0, 0, 0, 0);
            if (gr < NN) {
                size_t gi = (size_t)gr * KPAD + k8 * 8;
                vh = *(const uint4*)(Ah + gi);
                vl = *(const uint4*)(Al + gi);
            }
            *(uint4*)(sAh + r * SMS + k8 * 8) = vh;
            *(uint4*)(sAl + r * SMS + k8 * 8) = vl;
        }
        __syncthreads();

        float acc[MF][NF][4];
#pragma unroll
        for (int m = 0; m < MF; m++)
#pragma unroll
            for (int nf = 0; nf < NF; nf++)
#pragma unroll
                for (int j = 0; j < 4; j++) acc[m][nf][j] = 0.f;

#pragma unroll 1
        for (int pass = 0; pass < 3; pass++) {
            const uint32_t uA = (pass == 2) ? uAl : uAh;
            const uint32_t uW = (pass == 1) ? uWl : uWh;
#pragma unroll 1
            for (int ks = 0; ks < KS; ks++) {
                uint32_t af[MF][4];
#pragma unroll
                for (int m = 0; m < MF; m++)
                    ldmx4(af[m], uA + (uint32_t)(((a_row + m * 16) * SMS + ks * 16 + a_koff) * 2));
                uint32_t bf[NF][2];
#pragma unroll
                for (int nf = 0; nf < NF; nf++)
                    ldmx2(bf[nf], uW + (uint32_t)(((b_row + nf * 8) * SMS + ks * 16 + b_koff) * 2));
#pragma unroll
                for (int m = 0; m < MF; m++)
#pragma unroll
                    for (int nf = 0; nf < NF; nf++)
                        mma16816(acc[m][nf], af[m], bf[nf]);
            }
        }

        // ---- epilogue ----
#pragma unroll
        for (int m = 0; m < MF; m++) {
            int r0 = row0 + wm * WM + m * 16 + (lane >> 2);
#pragma unroll
            for (int nf = 0; nf < NF; nf++) {
                int c0 = wn * WN + nf * 8 + (lane & 3) * 2;
#pragma unroll
                for (int h = 0; h < 2; h++) {
                    int r = r0 + h * 8;
                    if (r >= NN) continue;
                    float d0 = acc[m][nf][2 * h], d1 = acc[m][nf][2 * h + 1];
                    if (EPI == 0) {
                        float v0 = 0.f, v1 = 0.f;
                        if (c0 < NOUT) {
                            v0 = fmaxf((d0 + p_b[c0])     * p_s[c0]     + p_e[c0],     0.f);
                            v1 = fmaxf((d1 + p_b[c0 + 1]) * p_s[c0 + 1] + p_e[c0 + 1], 0.f);
                        }
                        __nv_bfloat162 h2 = __floats2bfloat162_rn(v0, v1);
                        uint32_t uh = reinterpret_cast<uint32_t&>(h2);
                        uint32_t ul = pack_bf2(v0 - __low2float(h2), v1 - __high2float(h2));
                        *(uint32_t*)((char*)Oh + ((size_t)r * NCOV + c0) * 2) = uh;
                        *(uint32_t*)((char*)Ol + ((size_t)r * NCOV + c0) * 2) = ul;
                    } else {
                        if (c0 < NOUT) {
                            float2 y;
                            y.x = fmaxf(d0 + p_b[c0],     0.f);
                            y.y = fmaxf(d1 + p_b[c0 + 1], 0.f);
                            *(float2*)(Of + (size_t)r * 100 + c0) = y;
                        }
                    }
                }
            }
        }
        __syncthreads();
    }
}

// ---------------- readout ----------------
__global__ void ro_init_kernel() {
    int i = blockIdx.x * blockDim.x + threadIdx.x;
    if (i < NG * FD) { g_rosum[i] = 0.f; g_romax[i] = 0u; }
}

__global__ void readout_acc_kernel(const float* __restrict__ h) {
    int t = blockIdx.x * blockDim.x + threadIdx.x;
    if (t >= NN * FD) return;
    int n = t / FD, f = t - n * FD;
    float v = h[t];
    int g = g_batch[n];
    atomicAdd(&g_rosum[g * FD + f], v);
    atomicMax(&g_romax[g * FD + f], __float_as_uint(v));
}

__global__ void readout_fin_kernel(float* __restrict__ encode) {
    int t = blockIdx.x * blockDim.x + threadIdx.x;
    if (t >= NG * FD) return;
    int g = t / FD, f = t - g * FD;
    float cnt  = (float)g_gcnt[g];
    float mean = g_rosum[t] / fmaxf(cnt, 1.0f);
    float mx   = __uint_as_float(g_romax[t]);
    encode[g * FD2 + f]      += fmaxf(mean, 0.f);
    encode[g * FD2 + FD + f] += fmaxf(mx,   0.f);
}

// ---------------- head ----------------
__global__ void head_kernel(const float* __restrict__ encode,
                            const float* __restrict__ fc1_w, const float* __restrict__ fc1_b,
                            const float* __restrict__ cls_w, const float* __restrict__ cls_b,
                            float* __restrict__ logits) {
    __shared__ float enc[200];
    __shared__ float z[100];
    int g = blockIdx.x, t = threadIdx.x;
    for (int i = t; i < 200; i += 128) enc[i] = encode[g * 200 + i];
    __syncthreads();
    if (t < 100) {
        float a = fc1_b[t];
#pragma unroll 4
        for (int k = 0; k < 200; k++) a += enc[k] * __ldg(&fc1_w[t * 200 + k]);
        z[t] = fmaxf(a, 0.f);
    }
    __syncthreads();
    if (t < 64) {
        int o = t >> 5, lane = t & 31;
        float s = 0.f;
        for (int j = lane; j < 100; j += 32) s += z[j] * __ldg(&cls_w[o * 100 + j]);
#pragma unroll
        for (int off = 16; off; off >>= 1) s += __shfl_down_sync(0xffffffffu, s, off);
        if (lane == 0) logits[g * 2 + o] = s + cls_b[o];
    }
}

// ---------------- launch ----------------
extern "C" void kernel_launch(void* const* d_in, const int* in_sizes, int n_in,
                              void* d_out, int out_size) {
    const float* x       = (const float*)d_in[0];
    const void*  ei      = d_in[1];
    const void*  bt      = d_in[2];
    const float* c1_src_w = (const float*)d_in[3];
    const float* c1_src_b = (const float*)d_in[4];
    const float* c1_dst_w = (const float*)d_in[5];
    const float* c1_dst_b = (const float*)d_in[6];
    const float* cw1[3] = { (const float*)d_in[7],  (const float*)d_in[13], (const float*)d_in[19] };
    const float* cb1[3] = { (const float*)d_in[8],  (const float*)d_in[14], (const float*)d_in[20] };
    const float* cg [3] = { (const float*)d_in[9],  (const float*)d_in[15], (const float*)d_in[21] };
    const float* cbe[3] = { (const float*)d_in[10], (const float*)d_in[16], (const float*)d_in[22] };
    const float* cw2[3] = { (const float*)d_in[11], (const float*)d_in[17], (const float*)d_in[23] };
    const float* cb2[3] = { (const float*)d_in[12], (const float*)d_in[18], (const float*)d_in[24] };
    const float* fc1_w = (const float*)d_in[25];
    const float* fc1_b = (const float*)d_in[26];
    const float* cls_w = (const float*)d_in[27];
    const float* cls_b = (const float*)d_in[28];

    float* out    = (float*)d_out;
    float* logits = out;
    float* encode = out + NG * 2;

    float *pm, *pxd, *pout, *ph;
    cudaGetSymbolAddress((void**)&pm,   g_m);
    cudaGetSymbolAddress((void**)&pxd,  g_xd);
    cudaGetSymbolAddress((void**)&pout, g_out);
    cudaGetSymbolAddress((void**)&ph,   g_h);
    __nv_bfloat16 *pa1h, *pa1l, *pa2h, *pa2l, *pw1h, *pw1l, *pw2h, *pw2l;
    cudaGetSymbolAddress((void**)&pa1h, g_a1h);
    cudaGetSymbolAddress((void**)&pa1l, g_a1l);
    cudaGetSymbolAddress((void**)&pa2h, g_a2h);
    cudaGetSymbolAddress((void**)&pa2l, g_a2l);
    cudaGetSymbolAddress((void**)&pw1h, g_w1h);
    cudaGetSymbolAddress((void**)&pw1l, g_w1l);
    cudaGetSymbolAddress((void**)&pw2h, g_w2h);
    cudaGetSymbolAddress((void**)&pw2l, g_w2l);

    // GEMM1: <200,208,112,120,128,2,13,4,0>  smem = 2496 + 2*128*120*2 + 2*208*120*2 = 163776
    // GEMM2: <100,112,208,248,64,1,7,4,1>    smem = 1344 + 2*64*248*2  + 2*112*248*2 = 175936
    const int SM1 = (3 * NC1 * 4 + 15 & ~15) + 2 * 128 * 120 * 2 + 2 * NC1 * 120 * 2;
    const int SM2 = (3 * NC2 * 4 + 15 & ~15) + 2 * 64 * 248 * 2 + 2 * NC2 * 248 * 2;
    cudaFuncSetAttribute(mma_gemm_kernel<200, NC1, KP1, 120, 128, 2, 13, 4, 0>,
                         cudaFuncAttributeMaxDynamicSharedMemorySize, SM1);
    cudaFuncSetAttribute(mma_gemm_kernel<100, NC2, KP2, 248, 64, 1, 7, 4, 1>,
                         cudaFuncAttributeMaxDynamicSharedMemorySize, SM2);

    const int TB = 256;
    const int GE  = (NE + TB - 1) / TB;
    const int GNF = (NN * FD + TB - 1) / TB;
    const int GGF = (NG * FD + TB - 1) / TB;
    const int GSP = (NN * KP1 + TB - 1) / TB;
    const int NB_SCAN = (NN + 1023) / 1024;
    const int GEMM_GRID = 148;

    // CSR build (dst identical across convs -> build once)
    detect_kernel<<<1, 1024>>>((const unsigned long long*)ei);
    prep_kernel<<<GE, TB>>>(ei, bt, out);
    hist_kernel<<<GE, TB>>>();
    scan_block_kernel<<<NB_SCAN, 1024>>>();
    scan_bsums_kernel<<<1, 32>>>(NB_SCAN);
    scan_add_kernel<<<(NN + TB - 1) / TB, TB>>>();
    scatter_kernel<<<GE, TB>>>();

    // weight hi/lo prep
    for (int c = 0; c < 3; c++) {
        prep_w_kernel<<<(NC1 * KP1 + TB - 1) / TB, TB>>>(cw1[c], pw1h + c * NC1 * KP1,
                                                         pw1l + c * NC1 * KP1, 200, 100, KP1, NC1 * KP1);
        prep_w_kernel<<<(NC2 * KP2 + TB - 1) / TB, TB>>>(cw2[c], pw2h + c * NC2 * KP2,
                                                         pw2l + c * NC2 * KP2, 100, 200, KP2, NC2 * KP2);
    }

    // ---- conv1 ----
    lin10_kernel<<<GNF, TB>>>(x, c1_src_w, c1_src_b, c1_dst_w, c1_dst_b, pm, pxd);
    agg_kernel<false><<<(NN * 32 + TB - 1) / TB, TB>>>(pm, pxd, pout);
    split_a_kernel<<<GSP, TB>>>(pout, pa1h, pa1l);
    mma_gemm_kernel<200, NC1, KP1, 120, 128, 2, 13, 4, 0><<<GEMM_GRID, 256, SM1>>>(
        pa1h, pa1l, pw1h, pw1l, cb1[0], cg[0], cbe[0], pa2h, pa2l, nullptr);
    mma_gemm_kernel<100, NC2, KP2, 248, 64, 1, 7, 4, 1><<<GEMM_GRID, 256, SM2>>>(
        pa2h, pa2l, pw2h, pw2l, cb2[0], nullptr, nullptr, nullptr, nullptr, ph);
    ro_init_kernel<<<GGF, TB>>>();
    readout_acc_kernel<<<GNF, TB>>>(ph);
    readout_fin_kernel<<<GGF, TB>>>(encode);

    // ---- conv2 / conv3 ----
    for (int c = 1; c < 3; c++) {
        agg_kernel<true><<<(NN * 32 + TB - 1) / TB, TB>>>(ph, ph, pout);
        split_a_kernel<<<GSP, TB>>>(pout, pa1h, pa1l);
        mma_gemm_kernel<200, NC1, KP1, 120, 128, 2, 13, 4, 0><<<GEMM_GRID, 256, SM1>>>(
            pa1h, pa1l, pw1h + c * NC1 * KP1, pw1l + c * NC1 * KP1,
            cb1[c], cg[c], cbe[c], pa2h, pa2l, nullptr);
        mma_gemm_kernel<100, NC2, KP2, 248, 64, 1, 7, 4, 1><<<GEMM_GRID, 256, SM2>>>(
            pa2h, pa2l, pw2h + c * NC2 * KP2, pw2l + c * NC2 * KP2,
            cb2[c], nullptr, nullptr, nullptr, nullptr, ph);
        ro_init_kernel<<<GGF, TB>>>();
        readout_acc_kernel<<<GNF, TB>>>(ph);
        readout_fin_kernel<<<GGF, TB>>>(encode);
    }

    head_kernel<<<NG, 128>>>(encode, fc1_w, fc1_b, cls_w, cls_b, logits);
}

// round 10
// speedup vs baseline: 1.3080x; 1.0683x over previous
#include <cuda_runtime.h>
#include <cuda_bf16.h>
#include <cstdint>

#define NN 100000
#define NE 1600000
#define NG 512
#define FD 100
#define FD2 200
#define OUTSZ (NG*2 + NG*200)

#define KP1 112   // GEMM1 K padded (100 -> 112)
#define NC1 208   // GEMM1 N covered (200 -> 208)
#define KP2 208   // GEMM2 K padded (200 -> 208)
#define NC2 112   // GEMM2 N covered (100 -> 112)

// ---------------- scratch (device globals; no allocation allowed) ----------------
__device__ float g_m [NN*FD];
__device__ float g_xd[NN*FD];
__device__ float g_h [NN*FD];
__device__ int   g_src[NE];
__device__ int   g_dst[NE];
__device__ int   g_col[NE];
__device__ int   g_rowptr[NN+1];
__device__ int   g_cursor[NN];
__device__ int   g_counts[NN];
__device__ int   g_batch[NN];
__device__ int   g_bsums[128];
__device__ int   g_boffs[128];
__device__ int   g_gcnt[NG];
__device__ int   g_grow[NG+1];   // batch CSR rowptr
__device__ int   g_gcur[NG];     // batch CSR cursor
__device__ int   g_glist[NN];    // node ids grouped by graph
__device__ int   g_is64;

// bf16 hi/lo split operands for tensor-core GEMMs
__device__ __nv_bfloat16 g_a1h[NN*KP1], g_a1l[NN*KP1];        // GEMM1 input  [NN,112]
__device__ __nv_bfloat16 g_a2h[NN*KP2], g_a2l[NN*KP2];        // GEMM2 input  [NN,208]
__device__ __nv_bfloat16 g_w1h[3*NC1*KP1], g_w1l[3*NC1*KP1];  // W1 [208,112]
__device__ __nv_bfloat16 g_w2h[3*NC2*KP2], g_w2l[3*NC2*KP2];  // W2 [112,208]

// ================= mma.sync helpers (baseline PTX, sm_80+) =================
__device__ __forceinline__ uint32_t smem_u32(const void* p) {
    uint32_t a;
    asm("{ .reg .u64 t; cvta.to.shared.u64 t, %1; cvt.u32.u64 %0, t; }" : "=r"(a) : "l"(p));
    return a;
}
__device__ __forceinline__ void ldmx4(uint32_t* a, uint32_t addr) {
    asm volatile("ldmatrix.sync.aligned.m8n8.x4.shared.b16 {%0,%1,%2,%3}, [%4];"
        : "=r"(a[0]), "=r"(a[1]), "=r"(a[2]), "=r"(a[3]) : "r"(addr));
}
__device__ __forceinline__ void ldmx2(uint32_t* b, uint32_t addr) {
    asm volatile("ldmatrix.sync.aligned.m8n8.x2.shared.b16 {%0,%1}, [%2];"
        : "=r"(b[0]), "=r"(b[1]) : "r"(addr));
}
__device__ __forceinline__ void mma16816(float* d, const uint32_t* a, const uint32_t* b) {
    asm volatile("mma.sync.aligned.m16n8k16.row.col.f32.bf16.bf16.f32 "
        "{%0,%1,%2,%3}, {%4,%5,%6,%7}, {%8,%9}, {%0,%1,%2,%3};"
        : "+f"(d[0]), "+f"(d[1]), "+f"(d[2]), "+f"(d[3])
        : "r"(a[0]), "r"(a[1]), "r"(a[2]), "r"(a[3]), "r"(b[0]), "r"(b[1]));
}
__device__ __forceinline__ uint32_t pack_bf2(float a, float b) {
    __nv_bfloat162 t = __floats2bfloat162_rn(a, b);
    return reinterpret_cast<uint32_t&>(t);
}
__device__ __forceinline__ void st_hilo(__nv_bfloat16* oh, __nv_bfloat16* ol,
                                        size_t idx, float v) {
    __nv_bfloat16 h = __float2bfloat16(v);
    oh[idx] = h;
    ol[idx] = __float2bfloat16(v - __bfloat162float(h));
}

// ---------------- dtype sniff ----------------
__global__ void detect_kernel(const unsigned long long* __restrict__ ei) {
    __shared__ int found;
    if (threadIdx.x == 0) found = 0;
    __syncthreads();
    unsigned long long v = ei[threadIdx.x];
    if ((v >> 32) != 0ULL) found = 1;
    __syncthreads();
    if (threadIdx.x == 0) g_is64 = found ? 0 : 1;
}

__global__ void prep_kernel(const void* __restrict__ ei, const void* __restrict__ bt,
                            float* __restrict__ out) {
    int i = blockIdx.x * blockDim.x + threadIdx.x;
    int is64 = g_is64;
    if (i < NE) {
        if (is64) {
            const long long* e = (const long long*)ei;
            g_src[i] = (int)e[i];
            g_dst[i] = (int)e[NE + i];
        } else {
            const int* e = (const int*)ei;
            g_src[i] = e[i];
            g_dst[i] = e[NE + i];
        }
    }
    if (i < NN) {
        if (is64) g_batch[i] = (int)((const long long*)bt)[i];
        else      g_batch[i] = ((const int*)bt)[i];
        g_counts[i] = 0;
    }
    if (i < NG)    g_gcnt[i] = 0;
    if (i < OUTSZ) out[i] = 0.0f;
}

__global__ void hist_kernel() {
    int i = blockIdx.x * blockDim.x + threadIdx.x;
    if (i < NE) atomicAdd(&g_counts[g_dst[i]], 1);
    if (i < NN) atomicAdd(&g_gcnt[g_batch[i]], 1);
}

__global__ void scan_block_kernel() {
    __shared__ int sh[1024];
    int t = threadIdx.x;
    int i = blockIdx.x * 1024 + t;
    int v = (i < NN) ? g_counts[i] : 0;
    sh[t] = v;
    __syncthreads();
    for (int off = 1; off < 1024; off <<= 1) {
        int tmp = (t >= off) ? sh[t - off] : 0;
        __syncthreads();
        sh[t] += tmp;
        __syncthreads();
    }
    if (i < NN) g_rowptr[i] = sh[t] - v;
    if (t == 1023) g_bsums[blockIdx.x] = sh[1023];
}

// block 0: serial scan of per-block sums; block 1: scan of graph counts (batch CSR)
__global__ void scan_misc_kernel(int nb) {
    __shared__ int sg[NG];
    int t = threadIdx.x;
    if (blockIdx.x == 0) {
        if (t == 0) {
            int run = 0;
            for (int i = 0; i < nb; i++) { g_boffs[i] = run; run += g_bsums[i]; }
            g_rowptr[NN] = run;
        }
    } else {
        int v = (t < NG) ? g_gcnt[t] : 0;
        if (t < NG) sg[t] = v;
        __syncthreads();
        for (int off = 1; off < NG; off <<= 1) {
            int tmp = (t < NG && t >= off) ? sg[t - off] : 0;
            __syncthreads();
            if (t < NG) sg[t] += tmp;
            __syncthreads();
        }
        if (t < NG) { g_grow[t] = sg[t] - v; g_gcur[t] = sg[t] - v; }
        if (t == NG - 1) g_grow[NG] = sg[NG - 1];
    }
}

__global__ void scan_add_kernel() {
    int i = blockIdx.x * blockDim.x + threadIdx.x;
    if (i < NN) {
        int r = g_rowptr[i] + g_boffs[i >> 10];
        g_rowptr[i] = r;
        g_cursor[i] = r;
    }
}

__global__ void scatter_both_kernel() {
    int i = blockIdx.x * blockDim.x + threadIdx.x;
    if (i < NE) {
        int p = atomicAdd(&g_cursor[g_dst[i]], 1);
        g_col[p] = g_src[i];
    }
    if (i < NN) {
        int p = atomicAdd(&g_gcur[g_batch[i]], 1);
        g_glist[p] = i;
    }
}

// ---------------- weight hi/lo prep (all 6 panels in one kernel) ----------------
__global__ void prep_w_all_kernel(
    const float* __restrict__ w1a, const float* __restrict__ w1b, const float* __restrict__ w1c,
    const float* __restrict__ w2a, const float* __restrict__ w2b, const float* __restrict__ w2c,
    __nv_bfloat16* __restrict__ w1h, __nv_bfloat16* __restrict__ w1l,
    __nv_bfloat16* __restrict__ w2h, __nv_bfloat16* __restrict__ w2l) {
    const int S1 = NC1 * KP1, S2 = NC2 * KP2;
    int i = blockIdx.x * blockDim.x + threadIdx.x;
    if (i < 3 * S1) {
        int c = i / S1, r0 = i - c * S1;
        int r = r0 / KP1, k = r0 - r * KP1;
        const float* w = (c == 0) ? w1a : (c == 1) ? w1b : w1c;
        float v = (r < 200 && k < 100) ? w[r * 100 + k] : 0.f;
        st_hilo(w1h, w1l, i, v);
    } else {
        int j = i - 3 * S1;
        if (j >= 3 * S2) return;
        int c = j / S2, r0 = j - c * S2;
        int r = r0 / KP2, k = r0 - r * KP2;
        const float* w = (c == 0) ? w2a : (c == 1) ? w2b : w2c;
        float v = (r < 100 && k < 200) ? w[r * 200 + k] : 0.f;
        st_hilo(w2h, w2l, j, v);
    }
}

// ---------------- conv1 input linears ----------------
__global__ void lin10_kernel(const float* __restrict__ x,
                             const float* __restrict__ sw_, const float* __restrict__ sb_,
                             const float* __restrict__ dw_, const float* __restrict__ db_,
                             float* __restrict__ m_out, float* __restrict__ xd_out) {
    __shared__ float sw[1000], dw[1000], sb[100], db[100];
    int t = threadIdx.x;
    for (int i = t; i < 1000; i += blockDim.x) { sw[i] = sw_[i]; dw[i] = dw_[i]; }
    for (int i = t; i < 100;  i += blockDim.x) { sb[i] = sb_[i]; db[i] = db_[i]; }
    __syncthreads();
    int id = blockIdx.x * blockDim.x + t;
    if (id >= NN * FD) return;
    int n = id / FD, f = id - n * FD;
    float xs[10];
#pragma unroll
    for (int k = 0; k < 10; k++) xs[k] = x[n * 10 + k];
    float a = sb[f], b = db[f];
#pragma unroll
    for (int k = 0; k < 10; k++) { a += xs[k] * sw[f * 10 + k]; b += xs[k] * dw[f * 10 + k]; }
    m_out[id]  = fmaxf(a, 0.0f) + 1e-7f;
    xd_out[id] = b;
}

// ---------------- softmax aggregation (warp per dst node), fused bf16 hi/lo output ----------------
// Writes GEMM1 operand rows [KP1=112]: cols 0..99 = num/den + xd, cols 100..111 = 0.
template<bool TRANS>
__global__ void agg_kernel(const float* __restrict__ m, const float* __restrict__ xd,
                           __nv_bfloat16* __restrict__ oh, __nv_bfloat16* __restrict__ ol) {
    int w = (blockIdx.x * blockDim.x + threadIdx.x) >> 5;
    if (w >= NN) return;
    int lane = threadIdx.x & 31;
    int beg = g_rowptr[w], end = g_rowptr[w + 1];

    float mx0 = 0.f, mx1 = 0.f, mx2 = 0.f, mx3 = 0.f;
    for (int i = beg; i < end; i++) {
        int s = __ldg(&g_col[i]);
        const float* r = m + (size_t)s * FD;
        float v0 = r[lane], v1 = r[lane + 32], v2 = r[lane + 64];
        float v3 = 0.f;
        if (lane < 4) v3 = r[lane + 96];
        if (TRANS) {
            v0 = fmaxf(v0, 0.f) + 1e-7f; v1 = fmaxf(v1, 0.f) + 1e-7f;
            v2 = fmaxf(v2, 0.f) + 1e-7f; v3 = fmaxf(v3, 0.f) + 1e-7f;
        }
        mx0 = fmaxf(mx0, v0); mx1 = fmaxf(mx1, v1);
        mx2 = fmaxf(mx2, v2); mx3 = fmaxf(mx3, v3);
    }
    float d0 = 0.f, d1 = 0.f, d2 = 0.f, d3 = 0.f;
    float n0 = 0.f, n1 = 0.f, n2 = 0.f, n3 = 0.f;
    for (int i = beg; i < end; i++) {
        int s = __ldg(&g_col[i]);
        const float* r = m + (size_t)s * FD;
        float v0 = r[lane], v1 = r[lane + 32], v2 = r[lane + 64];
        float v3 = 0.f;
        if (lane < 4) v3 = r[lane + 96];
        if (TRANS) {
            v0 = fmaxf(v0, 0.f) + 1e-7f; v1 = fmaxf(v1, 0.f) + 1e-7f;
            v2 = fmaxf(v2, 0.f) + 1e-7f; v3 = fmaxf(v3, 0.f) + 1e-7f;
        }
        float e0 = __expf(v0 - mx0), e1 = __expf(v1 - mx1);
        float e2 = __expf(v2 - mx2), e3 = __expf(v3 - mx3);
        d0 += e0; d1 += e1; d2 += e2; d3 += e3;
        n0 += e0 * v0; n1 += e1 * v1; n2 += e2 * v2; n3 += e3 * v3;
    }
    size_t xo = (size_t)w * FD;
    size_t o  = (size_t)w * KP1;
    st_hilo(oh, ol, o + lane,      n0 / (d0 + 1e-16f) + xd[xo + lane]);
    st_hilo(oh, ol, o + lane + 32, n1 / (d1 + 1e-16f) + xd[xo + lane + 32]);
    st_hilo(oh, ol, o + lane + 64, n2 / (d2 + 1e-16f) + xd[xo + lane + 64]);
    if (lane < 4) {
        st_hilo(oh, ol, o + lane + 96, n3 / (d3 + 1e-16f) + xd[xo + lane + 96]);
    } else if (lane < 16) {      // zero pad cols 100..111
        __nv_bfloat16 z = __float2bfloat16(0.f);
        oh[o + 96 + lane] = z;
        ol[o + 96 + lane] = z;
    }
}

// ============ persistent mma.sync bf16 GEMM: C[M, NCOV] = A @ W^T ============
// 3 error-compensated passes: AhWh + AhWl + AlWh, fp32 accumulate.
// SMS % 64 == 56 -> conflict-free ldmatrix.
// EPI 0: relu((acc+bias)*gamma*rsqrt(1+1e-5)+beta) -> bf16 hi/lo Oh/Ol [NN,NCOV]
// EPI 1: relu(acc+bias) -> fp32 Of [NN,100]
template<int NOUT, int NCOV, int KPAD, int SMS, int MT, int MF, int NF, int WARPS_M, int EPI>
__global__ __launch_bounds__(256, 1) void mma_gemm_kernel(
    const __nv_bfloat16* __restrict__ Ah, const __nv_bfloat16* __restrict__ Al,
    const __nv_bfloat16* __restrict__ Wh, const __nv_bfloat16* __restrict__ Wl,
    const float* __restrict__ bias, const float* __restrict__ gamma, const float* __restrict__ beta,
    __nv_bfloat16* __restrict__ Oh, __nv_bfloat16* __restrict__ Ol, float* __restrict__ Of) {

    constexpr int WM = MF * 16;
    constexpr int WN = NF * 8;
    constexpr int KC = KPAD / 8;
    constexpr int KS = KPAD / 16;
    constexpr int POFF = (3 * NCOV * 4 + 15) & ~15;

    extern __shared__ char sm[];
    float* p_b = (float*)sm;
    float* p_s = p_b + NCOV;
    float* p_e = p_s + NCOV;
    __nv_bfloat16* sAh = (__nv_bfloat16*)(sm + POFF);
    __nv_bfloat16* sAl = sAh + MT * SMS;
    __nv_bfloat16* sWh = sAl + MT * SMS;
    __nv_bfloat16* sWl = sWh + NCOV * SMS;

    const int tid = threadIdx.x, wid = tid >> 5, lane = tid & 31;
    const int wm = wid % WARPS_M, wn = wid / WARPS_M;

    const float rs = rsqrtf(1.0f + 1e-5f);
    for (int i = tid; i < NCOV; i += 256) {
        p_b[i] = (i < NOUT) ? bias[i] : 0.f;
        if (EPI == 0) {
            p_s[i] = (i < NOUT) ? gamma[i] * rs : 0.f;
            p_e[i] = (i < NOUT) ? beta[i] : 0.f;
        }
    }
    for (int u = tid; u < NCOV * KC; u += 256) {
        int r = u / KC, k8 = u - r * KC;
        size_t gi = (size_t)r * KPAD + k8 * 8;
        *(uint4*)(sWh + r * SMS + k8 * 8) = *(const uint4*)(Wh + gi);
        *(uint4*)(sWl + r * SMS + k8 * 8) = *(const uint4*)(Wl + gi);
    }
    __syncthreads();

    const uint32_t uAh = smem_u32(sAh), uAl = smem_u32(sAl);
    const uint32_t uWh = smem_u32(sWh), uWl = smem_u32(sWl);
    const int a_row  = wm * WM + (lane & 15);
    const int a_koff = (lane >> 4) * 8;
    const int b_row  = wn * WN + (lane & 7);
    const int b_koff = ((lane >> 3) & 1) * 8;

    const int NT = (NN + MT - 1) / MT;
    for (int tile = blockIdx.x; tile < NT; tile += gridDim.x) {
        const int row0 = tile * MT;
        for (int u = tid; u < MT * KC; u += 256) {
            int r = u / KC, k8 = u - r * KC;
            int gr = row0 + r;
            uint4 vh = make_uint4(0, 0, 0, 0), vl = make_uint4(0, 0, 0, 0);
            if (gr < NN) {
                size_t gi = (size_t)gr * KPAD + k8 * 8;
                vh = *(const uint4*)(Ah + gi);
                vl = *(const uint4*)(Al + gi);
            }
            *(uint4*)(sAh + r * SMS + k8 * 8) = vh;
            *(uint4*)(sAl + r * SMS + k8 * 8) = vl;
        }
        __syncthreads();

        float acc[MF][NF][4];
#pragma unroll
        for (int m = 0; m < MF; m++)
#pragma unroll
            for (int nf = 0; nf < NF; nf++)
#pragma unroll
                for (int j = 0; j < 4; j++) acc[m][nf][j] = 0.f;

#pragma unroll 1
        for (int pass = 0; pass < 3; pass++) {
            const uint32_t uA = (pass == 2) ? uAl : uAh;
            const uint32_t uW = (pass == 1) ? uWl : uWh;
#pragma unroll 1
            for (int ks = 0; ks < KS; ks++) {
                uint32_t af[MF][4];
#pragma unroll
                for (int m = 0; m < MF; m++)
                    ldmx4(af[m], uA + (uint32_t)(((a_row + m * 16) * SMS + ks * 16 + a_koff) * 2));
                uint32_t bf[NF][2];
#pragma unroll
                for (int nf = 0; nf < NF; nf++)
                    ldmx2(bf[nf], uW + (uint32_t)(((b_row + nf * 8) * SMS + ks * 16 + b_koff) * 2));
#pragma unroll
                for (int m = 0; m < MF; m++)
#pragma unroll
                    for (int nf = 0; nf < NF; nf++)
                        mma16816(acc[m][nf], af[m], bf[nf]);
            }
        }

#pragma unroll
        for (int m = 0; m < MF; m++) {
            int r0 = row0 + wm * WM + m * 16 + (lane >> 2);
#pragma unroll
            for (int nf = 0; nf < NF; nf++) {
                int c0 = wn * WN + nf * 8 + (lane & 3) * 2;
#pragma unroll
                for (int h = 0; h < 2; h++) {
                    int r = r0 + h * 8;
                    if (r >= NN) continue;
                    float d0 = acc[m][nf][2 * h], d1 = acc[m][nf][2 * h + 1];
                    if (EPI == 0) {
                        float v0 = 0.f, v1 = 0.f;
                        if (c0 < NOUT) {
                            v0 = fmaxf((d0 + p_b[c0])     * p_s[c0]     + p_e[c0],     0.f);
                            v1 = fmaxf((d1 + p_b[c0 + 1]) * p_s[c0 + 1] + p_e[c0 + 1], 0.f);
                        }
                        __nv_bfloat162 h2 = __floats2bfloat162_rn(v0, v1);
                        uint32_t uh = reinterpret_cast<uint32_t&>(h2);
                        uint32_t ul = pack_bf2(v0 - __low2float(h2), v1 - __high2float(h2));
                        *(uint32_t*)((char*)Oh + ((size_t)r * NCOV + c0) * 2) = uh;
                        *(uint32_t*)((char*)Ol + ((size_t)r * NCOV + c0) * 2) = ul;
                    } else {
                        if (c0 < NOUT) {
                            float2 y;
                            y.x = fmaxf(d0 + p_b[c0],     0.f);
                            y.y = fmaxf(d1 + p_b[c0 + 1], 0.f);
                            *(float2*)(Of + (size_t)r * 100 + c0) = y;
                        }
                    }
                }
            }
        }
        __syncthreads();
    }
}

// ---------------- readout: block per graph, atomic-free segment sum/max ----------------
__global__ void readout_seg_kernel(const float* __restrict__ h, float* __restrict__ encode) {
    int g = blockIdx.x, t = threadIdx.x;
    if (t >= 100) return;
    int beg = g_grow[g], end = g_grow[g + 1];
    float s = 0.f, mx = 0.f;
    int i = beg;
    for (; i + 3 < end; i += 4) {
        int n0 = g_glist[i], n1 = g_glist[i + 1], n2 = g_glist[i + 2], n3 = g_glist[i + 3];
        float v0 = __ldg(&h[(size_t)n0 * FD + t]);
        float v1 = __ldg(&h[(size_t)n1 * FD + t]);
        float v2 = __ldg(&h[(size_t)n2 * FD + t]);
        float v3 = __ldg(&h[(size_t)n3 * FD + t]);
        s += v0 + v1 + v2 + v3;
        mx = fmaxf(mx, fmaxf(fmaxf(v0, v1), fmaxf(v2, v3)));
    }
    for (; i < end; i++) {
        float v = __ldg(&h[(size_t)g_glist[i] * FD + t]);
        s += v; mx = fmaxf(mx, v);
    }
    float cnt = (float)(end - beg);
    float mean = s / fmaxf(cnt, 1.0f);
    encode[g * FD2 + t]      += fmaxf(mean, 0.f);   // h >= 0, relu is identity, keep for safety
    encode[g * FD2 + FD + t] += fmaxf(mx,   0.f);
}

// ---------------- head ----------------
__global__ void head_kernel(const float* __restrict__ encode,
                            const float* __restrict__ fc1_w, const float* __restrict__ fc1_b,
                            const float* __restrict__ cls_w, const float* __restrict__ cls_b,
                            float* __restrict__ logits) {
    __shared__ float enc[200];
    __shared__ float z[100];
    int g = blockIdx.x, t = threadIdx.x;
    for (int i = t; i < 200; i += 128) enc[i] = encode[g * 200 + i];
    __syncthreads();
    if (t < 100) {
        float a = fc1_b[t];
#pragma unroll 4
        for (int k = 0; k < 200; k++) a += enc[k] * __ldg(&fc1_w[t * 200 + k]);
        z[t] = fmaxf(a, 0.f);
    }
    __syncthreads();
    if (t < 64) {
        int o = t >> 5, lane = t & 31;
        float s = 0.f;
        for (int j = lane; j < 100; j += 32) s += z[j] * __ldg(&cls_w[o * 100 + j]);
#pragma unroll
        for (int off = 16; off; off >>= 1) s += __shfl_down_sync(0xffffffffu, s, off);
        if (lane == 0) logits[g * 2 + o] = s + cls_b[o];
    }
}

// ---------------- launch ----------------
extern "C" void kernel_launch(void* const* d_in, const int* in_sizes, int n_in,
                              void* d_out, int out_size) {
    const float* x       = (const float*)d_in[0];
    const void*  ei      = d_in[1];
    const void*  bt      = d_in[2];
    const float* c1_src_w = (const float*)d_in[3];
    const float* c1_src_b = (const float*)d_in[4];
    const float* c1_dst_w = (const float*)d_in[5];
    const float* c1_dst_b = (const float*)d_in[6];
    const float* cw1[3] = { (const float*)d_in[7],  (const float*)d_in[13], (const float*)d_in[19] };
    const float* cb1[3] = { (const float*)d_in[8],  (const float*)d_in[14], (const float*)d_in[20] };
    const float* cg [3] = { (const float*)d_in[9],  (const float*)d_in[15], (const float*)d_in[21] };
    const float* cbe[3] = { (const float*)d_in[10], (const float*)d_in[16], (const float*)d_in[22] };
    const float* cw2[3] = { (const float*)d_in[11], (const float*)d_in[17], (const float*)d_in[23] };
    const float* cb2[3] = { (const float*)d_in[12], (const float*)d_in[18], (const float*)d_in[24] };
    const float* fc1_w = (const float*)d_in[25];
    const float* fc1_b = (const float*)d_in[26];
    const float* cls_w = (const float*)d_in[27];
    const float* cls_b = (const float*)d_in[28];

    float* out    = (float*)d_out;
    float* logits = out;
    float* encode = out + NG * 2;

    float *pm, *pxd, *ph;
    cudaGetSymbolAddress((void**)&pm,   g_m);
    cudaGetSymbolAddress((void**)&pxd,  g_xd);
    cudaGetSymbolAddress((void**)&ph,   g_h);
    __nv_bfloat16 *pa1h, *pa1l, *pa2h, *pa2l, *pw1h, *pw1l, *pw2h, *pw2l;
    cudaGetSymbolAddress((void**)&pa1h, g_a1h);
    cudaGetSymbolAddress((void**)&pa1l, g_a1l);
    cudaGetSymbolAddress((void**)&pa2h, g_a2h);
    cudaGetSymbolAddress((void**)&pa2l, g_a2l);
    cudaGetSymbolAddress((void**)&pw1h, g_w1h);
    cudaGetSymbolAddress((void**)&pw1l, g_w1l);
    cudaGetSymbolAddress((void**)&pw2h, g_w2h);
    cudaGetSymbolAddress((void**)&pw2l, g_w2l);

    // GEMM1: <200,208,112,120,128,2,13,4,0>  GEMM2: <100,112,208,248,64,1,7,4,1>
    const int SM1 = ((3 * NC1 * 4 + 15) & ~15) + 2 * 128 * 120 * 2 + 2 * NC1 * 120 * 2;
    const int SM2 = ((3 * NC2 * 4 + 15) & ~15) + 2 * 64 * 248 * 2 + 2 * NC2 * 248 * 2;
    cudaFuncSetAttribute(mma_gemm_kernel<200, NC1, KP1, 120, 128, 2, 13, 4, 0>,
                         cudaFuncAttributeMaxDynamicSharedMemorySize, SM1);
    cudaFuncSetAttribute(mma_gemm_kernel<100, NC2, KP2, 248, 64, 1, 7, 4, 1>,
                         cudaFuncAttributeMaxDynamicSharedMemorySize, SM2);

    const int TB = 256;
    const int GE  = (NE + TB - 1) / TB;
    const int GNF = (NN * FD + TB - 1) / TB;
    const int NB_SCAN = (NN + 1023) / 1024;
    const int GEMM_GRID = 148;
    const int WTOT = 3 * (NC1 * KP1 + NC2 * KP2);

    // CSR build (dst identical across convs -> build once) + batch CSR for readout
    detect_kernel<<<1, 1024>>>((const unsigned long long*)ei);
    prep_kernel<<<GE, TB>>>(ei, bt, out);
    hist_kernel<<<GE, TB>>>();
    scan_block_kernel<<<NB_SCAN, 1024>>>();
    scan_misc_kernel<<<2, 1024>>>(NB_SCAN);
    scan_add_kernel<<<(NN + TB - 1) / TB, TB>>>();
    scatter_both_kernel<<<GE, TB>>>();
    prep_w_all_kernel<<<(WTOT + TB - 1) / TB, TB>>>(cw1[0], cw1[1], cw1[2],
                                                    cw2[0], cw2[1], cw2[2],
                                                    pw1h, pw1l, pw2h, pw2l);

    // ---- conv1 ----
    lin10_kernel<<<GNF, TB>>>(x, c1_src_w, c1_src_b, c1_dst_w, c1_dst_b, pm, pxd);
    agg_kernel<false><<<(NN * 32 + TB - 1) / TB, TB>>>(pm, pxd, pa1h, pa1l);
    mma_gemm_kernel<200, NC1, KP1, 120, 128, 2, 13, 4, 0><<<GEMM_GRID, 256, SM1>>>(
        pa1h, pa1l, pw1h, pw1l, cb1[0], cg[0], cbe[0], pa2h, pa2l, nullptr);
    mma_gemm_kernel<100, NC2, KP2, 248, 64, 1, 7, 4, 1><<<GEMM_GRID, 256, SM2>>>(
        pa2h, pa2l, pw2h, pw2l, cb2[0], nullptr, nullptr, nullptr, nullptr, ph);
    readout_seg_kernel<<<NG, 128>>>(ph, encode);

    // ---- conv2 / conv3 ----
    for (int c = 1; c < 3; c++) {
        agg_kernel<true><<<(NN * 32 + TB - 1) / TB, TB>>>(ph, ph, pa1h, pa1l);
        mma_gemm_kernel<200, NC1, KP1, 120, 128, 2, 13, 4, 0><<<GEMM_GRID, 256, SM1>>>(
            pa1h, pa1l, pw1h + c * NC1 * KP1, pw1l + c * NC1 * KP1,
            cb1[c], cg[c], cbe[c], pa2h, pa2l, nullptr);
        mma_gemm_kernel<100, NC2, KP2, 248, 64, 1, 7, 4, 1><<<GEMM_GRID, 256, SM2>>>(
            pa2h, pa2l, pw2h + c * NC2 * KP2, pw2l + c * NC2 * KP2,
            cb2[c], nullptr, nullptr, nullptr, nullptr, ph);
        readout_seg_kernel<<<NG, 128>>>(ph, encode);
    }

    head_kernel<<<NG, 128>>>(encode, fc1_w, fc1_b, cls_w, cls_b, logits);
}

// round 11
// speedup vs baseline: 1.3237x; 1.0120x over previous
#include <cuda_runtime.h>
#include <cuda_bf16.h>
#include <cstdint>

#define NN 100000
#define NE 1600000
#define NG 512
#define FD 100
#define FD2 200
#define OUTSZ (NG*2 + NG*200)

#define KP1 112   // GEMM1 K padded (100 -> 112)
#define NC1 208   // GEMM1 N covered (200 -> 208)
#define KP2 208   // GEMM2 K padded (200 -> 208)
#define NC2 112   // GEMM2 N covered (100 -> 112)

// ---------------- scratch (device globals; no allocation allowed) ----------------
__device__ float g_m [NN*FD];
__device__ float g_xd[NN*FD];
__device__ float g_h [NN*FD];
__device__ int   g_src[NE];
__device__ int   g_dst[NE];
__device__ int   g_col[NE];
__device__ int   g_rowptr[NN+1];
__device__ int   g_cursor[NN];
__device__ int   g_counts[NN];
__device__ int   g_batch[NN];
__device__ int   g_bsums[128];
__device__ int   g_boffs[128];
__device__ int   g_gcnt[NG];
__device__ int   g_grow[NG+1];   // batch CSR rowptr
__device__ int   g_gcur[NG];     // batch CSR cursor
__device__ int   g_glist[NN];    // node ids grouped by graph
__device__ int   g_is64;

// bf16 hi/lo split operands for tensor-core GEMMs
__device__ __nv_bfloat16 g_a1h[NN*KP1], g_a1l[NN*KP1];        // GEMM1 input  [NN,112]
__device__ __nv_bfloat16 g_a2h[NN*KP2], g_a2l[NN*KP2];        // GEMM2 input  [NN,208]
__device__ __nv_bfloat16 g_w1h[3*NC1*KP1], g_w1l[3*NC1*KP1];  // W1 [208,112]
__device__ __nv_bfloat16 g_w2h[3*NC2*KP2], g_w2l[3*NC2*KP2];  // W2 [112,208]

// ================= mma.sync helpers (baseline PTX, sm_80+) =================
__device__ __forceinline__ uint32_t smem_u32(const void* p) {
    uint32_t a;
    asm("{ .reg .u64 t; cvta.to.shared.u64 t, %1; cvt.u32.u64 %0, t; }" : "=r"(a) : "l"(p));
    return a;
}
__device__ __forceinline__ void ldmx4(uint32_t* a, uint32_t addr) {
    asm volatile("ldmatrix.sync.aligned.m8n8.x4.shared.b16 {%0,%1,%2,%3}, [%4];"
        : "=r"(a[0]), "=r"(a[1]), "=r"(a[2]), "=r"(a[3]) : "r"(addr));
}
__device__ __forceinline__ void ldmx2(uint32_t* b, uint32_t addr) {
    asm volatile("ldmatrix.sync.aligned.m8n8.x2.shared.b16 {%0,%1}, [%2];"
        : "=r"(b[0]), "=r"(b[1]) : "r"(addr));
}
__device__ __forceinline__ void mma16816(float* d, const uint32_t* a, const uint32_t* b) {
    asm volatile("mma.sync.aligned.m16n8k16.row.col.f32.bf16.bf16.f32 "
        "{%0,%1,%2,%3}, {%4,%5,%6,%7}, {%8,%9}, {%0,%1,%2,%3};"
        : "+f"(d[0]), "+f"(d[1]), "+f"(d[2]), "+f"(d[3])
        : "r"(a[0]), "r"(a[1]), "r"(a[2]), "r"(a[3]), "r"(b[0]), "r"(b[1]));
}
__device__ __forceinline__ uint32_t pack_bf2(float a, float b) {
    __nv_bfloat162 t = __floats2bfloat162_rn(a, b);
    return reinterpret_cast<uint32_t&>(t);
}
__device__ __forceinline__ void st_hilo(__nv_bfloat16* oh, __nv_bfloat16* ol,
                                        size_t idx, float v) {
    __nv_bfloat16 h = __float2bfloat16(v);
    oh[idx] = h;
    ol[idx] = __float2bfloat16(v - __bfloat162float(h));
}
// online softmax update for one feature
__device__ __forceinline__ void onl(float v, float& mx, float& d, float& n) {
    float nm = fmaxf(mx, v);
    float s  = __expf(mx - nm);     // 1.0 when max unchanged
    float e  = __expf(v - nm);
    d = d * s + e;
    n = n * s + e * v;
    mx = nm;
}

// ---------------- dtype sniff ----------------
__global__ void detect_kernel(const unsigned long long* __restrict__ ei) {
    __shared__ int found;
    if (threadIdx.x == 0) found = 0;
    __syncthreads();
    unsigned long long v = ei[threadIdx.x];
    if ((v >> 32) != 0ULL) found = 1;
    __syncthreads();
    if (threadIdx.x == 0) g_is64 = found ? 0 : 1;
}

__global__ void prep_kernel(const void* __restrict__ ei, const void* __restrict__ bt,
                            float* __restrict__ out) {
    int i = blockIdx.x * blockDim.x + threadIdx.x;
    int is64 = g_is64;
    if (i < NE) {
        if (is64) {
            const long long* e = (const long long*)ei;
            g_src[i] = (int)e[i];
            g_dst[i] = (int)e[NE + i];
        } else {
            const int* e = (const int*)ei;
            g_src[i] = e[i];
            g_dst[i] = e[NE + i];
        }
    }
    if (i < NN) {
        if (is64) g_batch[i] = (int)((const long long*)bt)[i];
        else      g_batch[i] = ((const int*)bt)[i];
        g_counts[i] = 0;
    }
    if (i < NG)    g_gcnt[i] = 0;
    if (i < OUTSZ) out[i] = 0.0f;
}

__global__ void hist_kernel() {
    int i = blockIdx.x * blockDim.x + threadIdx.x;
    if (i < NE) atomicAdd(&g_counts[g_dst[i]], 1);
    if (i < NN) atomicAdd(&g_gcnt[g_batch[i]], 1);
}

__global__ void scan_block_kernel() {
    __shared__ int sh[1024];
    int t = threadIdx.x;
    int i = blockIdx.x * 1024 + t;
    int v = (i < NN) ? g_counts[i] : 0;
    sh[t] = v;
    __syncthreads();
    for (int off = 1; off < 1024; off <<= 1) {
        int tmp = (t >= off) ? sh[t - off] : 0;
        __syncthreads();
        sh[t] += tmp;
        __syncthreads();
    }
    if (i < NN) g_rowptr[i] = sh[t] - v;
    if (t == 1023) g_bsums[blockIdx.x] = sh[1023];
}

// block 0: serial scan of per-block sums; block 1: scan of graph counts (batch CSR)
__global__ void scan_misc_kernel(int nb) {
    __shared__ int sg[NG];
    int t = threadIdx.x;
    if (blockIdx.x == 0) {
        if (t == 0) {
            int run = 0;
            for (int i = 0; i < nb; i++) { g_boffs[i] = run; run += g_bsums[i]; }
            g_rowptr[NN] = run;
        }
    } else {
        int v = (t < NG) ? g_gcnt[t] : 0;
        if (t < NG) sg[t] = v;
        __syncthreads();
        for (int off = 1; off < NG; off <<= 1) {
            int tmp = (t < NG && t >= off) ? sg[t - off] : 0;
            __syncthreads();
            if (t < NG) sg[t] += tmp;
            __syncthreads();
        }
        if (t < NG) { g_grow[t] = sg[t] - v; g_gcur[t] = sg[t] - v; }
        if (t == NG - 1) g_grow[NG] = sg[NG - 1];
    }
}

__global__ void scan_add_kernel() {
    int i = blockIdx.x * blockDim.x + threadIdx.x;
    if (i < NN) {
        int r = g_rowptr[i] + g_boffs[i >> 10];
        g_rowptr[i] = r;
        g_cursor[i] = r;
    }
}

__global__ void scatter_both_kernel() {
    int i = blockIdx.x * blockDim.x + threadIdx.x;
    if (i < NE) {
        int p = atomicAdd(&g_cursor[g_dst[i]], 1);
        g_col[p] = g_src[i];
    }
    if (i < NN) {
        int p = atomicAdd(&g_gcur[g_batch[i]], 1);
        g_glist[p] = i;
    }
}

// ---------------- weight hi/lo prep (all 6 panels in one kernel) ----------------
__global__ void prep_w_all_kernel(
    const float* __restrict__ w1a, const float* __restrict__ w1b, const float* __restrict__ w1c,
    const float* __restrict__ w2a, const float* __restrict__ w2b, const float* __restrict__ w2c,
    __nv_bfloat16* __restrict__ w1h, __nv_bfloat16* __restrict__ w1l,
    __nv_bfloat16* __restrict__ w2h, __nv_bfloat16* __restrict__ w2l) {
    const int S1 = NC1 * KP1, S2 = NC2 * KP2;
    int i = blockIdx.x * blockDim.x + threadIdx.x;
    if (i < 3 * S1) {
        int c = i / S1, r0 = i - c * S1;
        int r = r0 / KP1, k = r0 - r * KP1;
        const float* w = (c == 0) ? w1a : (c == 1) ? w1b : w1c;
        float v = (r < 200 && k < 100) ? w[r * 100 + k] : 0.f;
        st_hilo(w1h, w1l, i, v);
    } else {
        int j = i - 3 * S1;
        if (j >= 3 * S2) return;
        int c = j / S2, r0 = j - c * S2;
        int r = r0 / KP2, k = r0 - r * KP2;
        const float* w = (c == 0) ? w2a : (c == 1) ? w2b : w2c;
        float v = (r < 100 && k < 200) ? w[r * 200 + k] : 0.f;
        st_hilo(w2h, w2l, j, v);
    }
}

// ---------------- conv1 input linears ----------------
__global__ void lin10_kernel(const float* __restrict__ x,
                             const float* __restrict__ sw_, const float* __restrict__ sb_,
                             const float* __restrict__ dw_, const float* __restrict__ db_,
                             float* __restrict__ m_out, float* __restrict__ xd_out) {
    __shared__ float sw[1000], dw[1000], sb[100], db[100];
    int t = threadIdx.x;
    for (int i = t; i < 1000; i += blockDim.x) { sw[i] = sw_[i]; dw[i] = dw_[i]; }
    for (int i = t; i < 100;  i += blockDim.x) { sb[i] = sb_[i]; db[i] = db_[i]; }
    __syncthreads();
    int id = blockIdx.x * blockDim.x + t;
    if (id >= NN * FD) return;
    int n = id / FD, f = id - n * FD;
    float xs[10];
#pragma unroll
    for (int k = 0; k < 10; k++) xs[k] = x[n * 10 + k];
    float a = sb[f], b = db[f];
#pragma unroll
    for (int k = 0; k < 10; k++) { a += xs[k] * sw[f * 10 + k]; b += xs[k] * dw[f * 10 + k]; }
    m_out[id]  = fmaxf(a, 0.0f) + 1e-7f;
    xd_out[id] = b;
}

// ---------------- softmax aggregation: ONLINE single-pass, warp per dst node ----------------
// Lane l (<25) owns features 4l..4l+3 (one float4 gather per edge).
// Writes GEMM1 operand rows [KP1=112] as bf16 hi/lo: cols 0..99 = num/den + xd, 100..111 = 0.
template<bool TRANS>
__global__ void agg_kernel(const float* __restrict__ m, const float* __restrict__ xd,
                           __nv_bfloat16* __restrict__ oh, __nv_bfloat16* __restrict__ ol) {
    int w = (blockIdx.x * blockDim.x + threadIdx.x) >> 5;
    if (w >= NN) return;
    int lane = threadIdx.x & 31;
    size_t orow = (size_t)w * KP1;

    if (lane < 25) {
        int beg = g_rowptr[w], end = g_rowptr[w + 1];
        float4 mx = make_float4(0.f, 0.f, 0.f, 0.f);
        float4 d  = make_float4(0.f, 0.f, 0.f, 0.f);
        float4 n  = make_float4(0.f, 0.f, 0.f, 0.f);
        for (int i = beg; i < end; i++) {
            int s = __ldg(&g_col[i]);
            float4 v = __ldg((const float4*)(m + (size_t)s * FD) + lane);
            if (TRANS) {
                v.x = fmaxf(v.x, 0.f) + 1e-7f; v.y = fmaxf(v.y, 0.f) + 1e-7f;
                v.z = fmaxf(v.z, 0.f) + 1e-7f; v.w = fmaxf(v.w, 0.f) + 1e-7f;
            }
            onl(v.x, mx.x, d.x, n.x);
            onl(v.y, mx.y, d.y, n.y);
            onl(v.z, mx.z, d.z, n.z);
            onl(v.w, mx.w, d.w, n.w);
        }
        float4 xv = __ldg((const float4*)(xd + (size_t)w * FD) + lane);
        float o0 = n.x / (d.x + 1e-16f) + xv.x;
        float o1 = n.y / (d.y + 1e-16f) + xv.y;
        float o2 = n.z / (d.z + 1e-16f) + xv.z;
        float o3 = n.w / (d.w + 1e-16f) + xv.w;
        __nv_bfloat162 h01 = __floats2bfloat162_rn(o0, o1);
        __nv_bfloat162 h23 = __floats2bfloat162_rn(o2, o3);
        uint2 hv, lv;
        hv.x = reinterpret_cast<uint32_t&>(h01);
        hv.y = reinterpret_cast<uint32_t&>(h23);
        lv.x = pack_bf2(o0 - __low2float(h01), o1 - __high2float(h01));
        lv.y = pack_bf2(o2 - __low2float(h23), o3 - __high2float(h23));
        *(uint2*)((char*)oh + (orow + 4 * lane) * 2) = hv;
        *(uint2*)((char*)ol + (orow + 4 * lane) * 2) = lv;
    } else if (lane < 28) {       // zero pad cols 100..111 (4*lane = 100,104,108)
        uint2 z = make_uint2(0u, 0u);
        *(uint2*)((char*)oh + (orow + 4 * lane) * 2) = z;
        *(uint2*)((char*)ol + (orow + 4 * lane) * 2) = z;
    }
}

// ============ persistent mma.sync bf16 GEMM: C[M, NCOV] = A @ W^T ============
// 3 error-compensated passes: AhWh + AhWl + AlWh, fp32 accumulate.
// SMS % 64 == 56 -> conflict-free ldmatrix.
// EPI 0: relu((acc+bias)*gamma*rsqrt(1+1e-5)+beta) -> bf16 hi/lo Oh/Ol [NN,NCOV]
// EPI 1: relu(acc+bias) -> fp32 Of [NN,100]
template<int NOUT, int NCOV, int KPAD, int SMS, int MT, int MF, int NF, int WARPS_M, int EPI>
__global__ __launch_bounds__(256, 1) void mma_gemm_kernel(
    const __nv_bfloat16* __restrict__ Ah, const __nv_bfloat16* __restrict__ Al,
    const __nv_bfloat16* __restrict__ Wh, const __nv_bfloat16* __restrict__ Wl,
    const float* __restrict__ bias, const float* __restrict__ gamma, const float* __restrict__ beta,
    __nv_bfloat16* __restrict__ Oh, __nv_bfloat16* __restrict__ Ol, float* __restrict__ Of) {

    constexpr int WM = MF * 16;
    constexpr int WN = NF * 8;
    constexpr int KC = KPAD / 8;
    constexpr int KS = KPAD / 16;
    constexpr int POFF = (3 * NCOV * 4 + 15) & ~15;

    extern __shared__ char sm[];
    float* p_b = (float*)sm;
    float* p_s = p_b + NCOV;
    float* p_e = p_s + NCOV;
    __nv_bfloat16* sAh = (__nv_bfloat16*)(sm + POFF);
    __nv_bfloat16* sAl = sAh + MT * SMS;
    __nv_bfloat16* sWh = sAl + MT * SMS;
    __nv_bfloat16* sWl = sWh + NCOV * SMS;

    const int tid = threadIdx.x, wid = tid >> 5, lane = tid & 31;
    const int wm = wid % WARPS_M, wn = wid / WARPS_M;

    const float rs = rsqrtf(1.0f + 1e-5f);
    for (int i = tid; i < NCOV; i += 256) {
        p_b[i] = (i < NOUT) ? bias[i] : 0.f;
        if (EPI == 0) {
            p_s[i] = (i < NOUT) ? gamma[i] * rs : 0.f;
            p_e[i] = (i < NOUT) ? beta[i] : 0.f;
        }
    }
    for (int u = tid; u < NCOV * KC; u += 256) {
        int r = u / KC, k8 = u - r * KC;
        size_t gi = (size_t)r * KPAD + k8 * 8;
        *(uint4*)(sWh + r * SMS + k8 * 8) = *(const uint4*)(Wh + gi);
        *(uint4*)(sWl + r * SMS + k8 * 8) = *(const uint4*)(Wl + gi);
    }
    __syncthreads();

    const uint32_t uAh = smem_u32(sAh), uAl = smem_u32(sAl);
    const uint32_t uWh = smem_u32(sWh), uWl = smem_u32(sWl);
    const int a_row  = wm * WM + (lane & 15);
    const int a_koff = (lane >> 4) * 8;
    const int b_row  = wn * WN + (lane & 7);
    const int b_koff = ((lane >> 3) & 1) * 8;

    const int NT = (NN + MT - 1) / MT;
    for (int tile = blockIdx.x; tile < NT; tile += gridDim.x) {
        const int row0 = tile * MT;
        for (int u = tid; u < MT * KC; u += 256) {
            int r = u / KC, k8 = u - r * KC;
            int gr = row0 + r;
            uint4 vh = make_uint4(0, 0, 0, 0), vl = make_uint4(0, 0, 0, 0);
            if (gr < NN) {
                size_t gi = (size_t)gr * KPAD + k8 * 8;
                vh = *(const uint4*)(Ah + gi);
                vl = *(const uint4*)(Al + gi);
            }
            *(uint4*)(sAh + r * SMS + k8 * 8) = vh;
            *(uint4*)(sAl + r * SMS + k8 * 8) = vl;
        }
        __syncthreads();

        float acc[MF][NF][4];
#pragma unroll
        for (int m = 0; m < MF; m++)
#pragma unroll
            for (int nf = 0; nf < NF; nf++)
#pragma unroll
                for (int j = 0; j < 4; j++) acc[m][nf][j] = 0.f;

#pragma unroll 1
        for (int pass = 0; pass < 3; pass++) {
            const uint32_t uA = (pass == 2) ? uAl : uAh;
            const uint32_t uW = (pass == 1) ? uWl : uWh;
#pragma unroll 1
            for (int ks = 0; ks < KS; ks++) {
                uint32_t af[MF][4];
#pragma unroll
                for (int m = 0; m < MF; m++)
                    ldmx4(af[m], uA + (uint32_t)(((a_row + m * 16) * SMS + ks * 16 + a_koff) * 2));
                uint32_t bf[NF][2];
#pragma unroll
                for (int nf = 0; nf < NF; nf++)
                    ldmx2(bf[nf], uW + (uint32_t)(((b_row + nf * 8) * SMS + ks * 16 + b_koff) * 2));
#pragma unroll
                for (int m = 0; m < MF; m++)
#pragma unroll
                    for (int nf = 0; nf < NF; nf++)
                        mma16816(acc[m][nf], af[m], bf[nf]);
            }
        }

#pragma unroll
        for (int m = 0; m < MF; m++) {
            int r0 = row0 + wm * WM + m * 16 + (lane >> 2);
#pragma unroll
            for (int nf = 0; nf < NF; nf++) {
                int c0 = wn * WN + nf * 8 + (lane & 3) * 2;
#pragma unroll
                for (int h = 0; h < 2; h++) {
                    int r = r0 + h * 8;
                    if (r >= NN) continue;
                    float d0 = acc[m][nf][2 * h], d1 = acc[m][nf][2 * h + 1];
                    if (EPI == 0) {
                        float v0 = 0.f, v1 = 0.f;
                        if (c0 < NOUT) {
                            v0 = fmaxf((d0 + p_b[c0])     * p_s[c0]     + p_e[c0],     0.f);
                            v1 = fmaxf((d1 + p_b[c0 + 1]) * p_s[c0 + 1] + p_e[c0 + 1], 0.f);
                        }
                        __nv_bfloat162 h2 = __floats2bfloat162_rn(v0, v1);
                        uint32_t uh = reinterpret_cast<uint32_t&>(h2);
                        uint32_t ul = pack_bf2(v0 - __low2float(h2), v1 - __high2float(h2));
                        *(uint32_t*)((char*)Oh + ((size_t)r * NCOV + c0) * 2) = uh;
                        *(uint32_t*)((char*)Ol + ((size_t)r * NCOV + c0) * 2) = ul;
                    } else {
                        if (c0 < NOUT) {
                            float2 y;
                            y.x = fmaxf(d0 + p_b[c0],     0.f);
                            y.y = fmaxf(d1 + p_b[c0 + 1], 0.f);
                            *(float2*)(Of + (size_t)r * 100 + c0) = y;
                        }
                    }
                }
            }
        }
        __syncthreads();
    }
}

// ---------------- readout: block per graph, atomic-free segment sum/max ----------------
__global__ void readout_seg_kernel(const float* __restrict__ h, float* __restrict__ encode) {
    int g = blockIdx.x, t = threadIdx.x;
    if (t >= 100) return;
    int beg = g_grow[g], end = g_grow[g + 1];
    float s = 0.f, mx = 0.f;
    int i = beg;
    for (; i + 3 < end; i += 4) {
        int n0 = g_glist[i], n1 = g_glist[i + 1], n2 = g_glist[i + 2], n3 = g_glist[i + 3];
        float v0 = __ldg(&h[(size_t)n0 * FD + t]);
        float v1 = __ldg(&h[(size_t)n1 * FD + t]);
        float v2 = __ldg(&h[(size_t)n2 * FD + t]);
        float v3 = __ldg(&h[(size_t)n3 * FD + t]);
        s += v0 + v1 + v2 + v3;
        mx = fmaxf(mx, fmaxf(fmaxf(v0, v1), fmaxf(v2, v3)));
    }
    for (; i < end; i++) {
        float v = __ldg(&h[(size_t)g_glist[i] * FD + t]);
        s += v; mx = fmaxf(mx, v);
    }
    float cnt = (float)(end - beg);
    float mean = s / fmaxf(cnt, 1.0f);
    encode[g * FD2 + t]      += fmaxf(mean, 0.f);
    encode[g * FD2 + FD + t] += fmaxf(mx,   0.f);
}

// ---------------- head ----------------
__global__ void head_kernel(const float* __restrict__ encode,
                            const float* __restrict__ fc1_w, const float* __restrict__ fc1_b,
                            const float* __restrict__ cls_w, const float* __restrict__ cls_b,
                            float* __restrict__ logits) {
    __shared__ float enc[200];
    __shared__ float z[100];
    int g = blockIdx.x, t = threadIdx.x;
    for (int i = t; i < 200; i += 128) enc[i] = encode[g * 200 + i];
    __syncthreads();
    if (t < 100) {
        float a = fc1_b[t];
#pragma unroll 4
        for (int k = 0; k < 200; k++) a += enc[k] * __ldg(&fc1_w[t * 200 + k]);
        z[t] = fmaxf(a, 0.f);
    }
    __syncthreads();
    if (t < 64) {
        int o = t >> 5, lane = t & 31;
        float s = 0.f;
        for (int j = lane; j < 100; j += 32) s += z[j] * __ldg(&cls_w[o * 100 + j]);
#pragma unroll
        for (int off = 16; off; off >>= 1) s += __shfl_down_sync(0xffffffffu, s, off);
        if (lane == 0) logits[g * 2 + o] = s + cls_b[o];
    }
}

// ---------------- launch ----------------
extern "C" void kernel_launch(void* const* d_in, const int* in_sizes, int n_in,
                              void* d_out, int out_size) {
    const float* x       = (const float*)d_in[0];
    const void*  ei      = d_in[1];
    const void*  bt      = d_in[2];
    const float* c1_src_w = (const float*)d_in[3];
    const float* c1_src_b = (const float*)d_in[4];
    const float* c1_dst_w = (const float*)d_in[5];
    const float* c1_dst_b = (const float*)d_in[6];
    const float* cw1[3] = { (const float*)d_in[7],  (const float*)d_in[13], (const float*)d_in[19] };
    const float* cb1[3] = { (const float*)d_in[8],  (const float*)d_in[14], (const float*)d_in[20] };
    const float* cg [3] = { (const float*)d_in[9],  (const float*)d_in[15], (const float*)d_in[21] };
    const float* cbe[3] = { (const float*)d_in[10], (const float*)d_in[16], (const float*)d_in[22] };
    const float* cw2[3] = { (const float*)d_in[11], (const float*)d_in[17], (const float*)d_in[23] };
    const float* cb2[3] = { (const float*)d_in[12], (const float*)d_in[18], (const float*)d_in[24] };
    const float* fc1_w = (const float*)d_in[25];
    const float* fc1_b = (const float*)d_in[26];
    const float* cls_w = (const float*)d_in[27];
    const float* cls_b = (const float*)d_in[28];

    float* out    = (float*)d_out;
    float* logits = out;
    float* encode = out + NG * 2;

    float *pm, *pxd, *ph;
    cudaGetSymbolAddress((void**)&pm,   g_m);
    cudaGetSymbolAddress((void**)&pxd,  g_xd);
    cudaGetSymbolAddress((void**)&ph,   g_h);
    __nv_bfloat16 *pa1h, *pa1l, *pa2h, *pa2l, *pw1h, *pw1l, *pw2h, *pw2l;
    cudaGetSymbolAddress((void**)&pa1h, g_a1h);
    cudaGetSymbolAddress((void**)&pa1l, g_a1l);
    cudaGetSymbolAddress((void**)&pa2h, g_a2h);
    cudaGetSymbolAddress((void**)&pa2l, g_a2l);
    cudaGetSymbolAddress((void**)&pw1h, g_w1h);
    cudaGetSymbolAddress((void**)&pw1l, g_w1l);
    cudaGetSymbolAddress((void**)&pw2h, g_w2h);
    cudaGetSymbolAddress((void**)&pw2l, g_w2l);

    // GEMM1: <200,208,112,120,128,2,13,4,0>  GEMM2: <100,112,208,248,64,1,7,4,1>
    const int SM1 = ((3 * NC1 * 4 + 15) & ~15) + 2 * 128 * 120 * 2 + 2 * NC1 * 120 * 2;
    const int SM2 = ((3 * NC2 * 4 + 15) & ~15) + 2 * 64 * 248 * 2 + 2 * NC2 * 248 * 2;
    cudaFuncSetAttribute(mma_gemm_kernel<200, NC1, KP1, 120, 128, 2, 13, 4, 0>,
                         cudaFuncAttributeMaxDynamicSharedMemorySize, SM1);
    cudaFuncSetAttribute(mma_gemm_kernel<100, NC2, KP2, 248, 64, 1, 7, 4, 1>,
                         cudaFuncAttributeMaxDynamicSharedMemorySize, SM2);

    const int TB = 256;
    const int GE  = (NE + TB - 1) / TB;
    const int GNF = (NN * FD + TB - 1) / TB;
    const int NB_SCAN = (NN + 1023) / 1024;
    const int GEMM_GRID = 148;
    const int WTOT = 3 * (NC1 * KP1 + NC2 * KP2);

    // CSR build (dst identical across convs -> build once) + batch CSR for readout
    detect_kernel<<<1, 1024>>>((const unsigned long long*)ei);
    prep_kernel<<<GE, TB>>>(ei, bt, out);
    hist_kernel<<<GE, TB>>>();
    scan_block_kernel<<<NB_SCAN, 1024>>>();
    scan_misc_kernel<<<2, 1024>>>(NB_SCAN);
    scan_add_kernel<<<(NN + TB - 1) / TB, TB>>>();
    scatter_both_kernel<<<GE, TB>>>();
    prep_w_all_kernel<<<(WTOT + TB - 1) / TB, TB>>>(cw1[0], cw1[1], cw1[2],
                                                    cw2[0], cw2[1], cw2[2],
                                                    pw1h, pw1l, pw2h, pw2l);

    // ---- conv1 ----
    lin10_kernel<<<GNF, TB>>>(x, c1_src_w, c1_src_b, c1_dst_w, c1_dst_b, pm, pxd);
    agg_kernel<false><<<(NN * 32 + TB - 1) / TB, TB>>>(pm, pxd, pa1h, pa1l);
    mma_gemm_kernel<200, NC1, KP1, 120, 128, 2, 13, 4, 0><<<GEMM_GRID, 256, SM1>>>(
        pa1h, pa1l, pw1h, pw1l, cb1[0], cg[0], cbe[0], pa2h, pa2l, nullptr);
    mma_gemm_kernel<100, NC2, KP2, 248, 64, 1, 7, 4, 1><<<GEMM_GRID, 256, SM2>>>(
        pa2h, pa2l, pw2h, pw2l, cb2[0], nullptr, nullptr, nullptr, nullptr, ph);
    readout_seg_kernel<<<NG, 128>>>(ph, encode);

    // ---- conv2 / conv3 ----
    for (int c = 1; c < 3; c++) {
        agg_kernel<true><<<(NN * 32 + TB - 1) / TB, TB>>>(ph, ph, pa1h, pa1l);
        mma_gemm_kernel<200, NC1, KP1, 120, 128, 2, 13, 4, 0><<<GEMM_GRID, 256, SM1>>>(
            pa1h, pa1l, pw1h + c * NC1 * KP1, pw1l + c * NC1 * KP1,
            cb1[c], cg[c], cbe[c], pa2h, pa2l, nullptr);
        mma_gemm_kernel<100, NC2, KP2, 248, 64, 1, 7, 4, 1><<<GEMM_GRID, 256, SM2>>>(
            pa2h, pa2l, pw2h + c * NC2 * KP2, pw2l + c * NC2 * KP2,
            cb2[c], nullptr, nullptr, nullptr, nullptr, ph);
        readout_seg_kernel<<<NG, 128>>>(ph, encode);
    }

    head_kernel<<<NG, 128>>>(encode, fc1_w, fc1_b, cls_w, cls_b, logits);
}

// round 12
// speedup vs baseline: 1.3380x; 1.0108x over previous
#include <cuda_runtime.h>
#include <cuda_bf16.h>
#include <cstdint>

#define NN 100000
#define NE 1600000
#define NG 512
#define FD 100
#define FD2 200
#define OUTSZ (NG*2 + NG*200)

#define KP1 112   // GEMM1 K padded (100 -> 112)
#define NC1 208   // GEMM1 N covered (200 -> 208)
#define KP2 208   // GEMM2 K padded (200 -> 208)
#define NC2 112   // GEMM2 N covered (100 -> 112)

// ---------------- scratch (device globals; no allocation allowed) ----------------
__device__ float g_m [NN*FD];
__device__ float g_xd[NN*FD];
__device__ float g_h [NN*FD];
__device__ int   g_src[NE];
__device__ int   g_dst[NE];
__device__ int   g_col[NE];
__device__ int   g_rowptr[NN+1];
__device__ int   g_cursor[NN];
__device__ int   g_counts[NN];
__device__ int   g_batch[NN];
__device__ int   g_bsums[128];
__device__ int   g_boffs[128];
__device__ int   g_gcnt[NG];
__device__ int   g_grow[NG+1];   // batch CSR rowptr
__device__ int   g_gcur[NG];     // batch CSR cursor
__device__ int   g_glist[NN];    // node ids grouped by graph
__device__ int   g_is64;

// bf16 hi/lo split operands for tensor-core GEMMs
__device__ __nv_bfloat16 g_a1h[NN*KP1], g_a1l[NN*KP1];        // GEMM1 input  [NN,112]
__device__ __nv_bfloat16 g_a2h[NN*KP2], g_a2l[NN*KP2];        // GEMM2 input  [NN,208]
__device__ __nv_bfloat16 g_w1h[3*NC1*KP1], g_w1l[3*NC1*KP1];  // W1 [208,112]
__device__ __nv_bfloat16 g_w2h[3*NC2*KP2], g_w2l[3*NC2*KP2];  // W2 [112,208]

// ================= mma.sync helpers (baseline PTX, sm_80+) =================
__device__ __forceinline__ uint32_t smem_u32(const void* p) {
    uint32_t a;
    asm("{ .reg .u64 t; cvta.to.shared.u64 t, %1; cvt.u32.u64 %0, t; }" : "=r"(a) : "l"(p));
    return a;
}
__device__ __forceinline__ void ldmx4(uint32_t* a, uint32_t addr) {
    asm volatile("ldmatrix.sync.aligned.m8n8.x4.shared.b16 {%0,%1,%2,%3}, [%4];"
        : "=r"(a[0]), "=r"(a[1]), "=r"(a[2]), "=r"(a[3]) : "r"(addr));
}
__device__ __forceinline__ void ldmx2(uint32_t* b, uint32_t addr) {
    asm volatile("ldmatrix.sync.aligned.m8n8.x2.shared.b16 {%0,%1}, [%2];"
        : "=r"(b[0]), "=r"(b[1]) : "r"(addr));
}
__device__ __forceinline__ void mma16816(float* d, const uint32_t* a, const uint32_t* b) {
    asm volatile("mma.sync.aligned.m16n8k16.row.col.f32.bf16.bf16.f32 "
        "{%0,%1,%2,%3}, {%4,%5,%6,%7}, {%8,%9}, {%0,%1,%2,%3};"
        : "+f"(d[0]), "+f"(d[1]), "+f"(d[2]), "+f"(d[3])
        : "r"(a[0]), "r"(a[1]), "r"(a[2]), "r"(a[3]), "r"(b[0]), "r"(b[1]));
}
__device__ __forceinline__ uint32_t pack_bf2(float a, float b) {
    __nv_bfloat162 t = __floats2bfloat162_rn(a, b);
    return reinterpret_cast<uint32_t&>(t);
}
__device__ __forceinline__ void st_hilo(__nv_bfloat16* oh, __nv_bfloat16* ol,
                                        size_t idx, float v) {
    __nv_bfloat16 h = __float2bfloat16(v);
    oh[idx] = h;
    ol[idx] = __float2bfloat16(v - __bfloat162float(h));
}
// online softmax update, ONE exp per call: e = exp(-|v-mx|)
__device__ __forceinline__ void onl(float v, float& mx, float& d, float& n) {
    float t = v - mx;
    float e = __expf(-fabsf(t));
    if (t <= 0.f) {            // max unchanged: accumulate scaled-down new term
        d += e;
        n += e * v;
    } else {                   // new max: rescale old accumulators
        d = d * e + 1.f;
        n = n * e + v;
        mx = v;
    }
}

// ---------------- dtype sniff ----------------
__global__ void detect_kernel(const unsigned long long* __restrict__ ei) {
    __shared__ int found;
    if (threadIdx.x == 0) found = 0;
    __syncthreads();
    unsigned long long v = ei[threadIdx.x];
    if ((v >> 32) != 0ULL) found = 1;
    __syncthreads();
    if (threadIdx.x == 0) g_is64 = found ? 0 : 1;
}

__global__ void prep_kernel(const void* __restrict__ ei, const void* __restrict__ bt,
                            float* __restrict__ out) {
    int i = blockIdx.x * blockDim.x + threadIdx.x;
    int is64 = g_is64;
    if (i < NE) {
        if (is64) {
            const long long* e = (const long long*)ei;
            g_src[i] = (int)e[i];
            g_dst[i] = (int)e[NE + i];
        } else {
            const int* e = (const int*)ei;
            g_src[i] = e[i];
            g_dst[i] = e[NE + i];
        }
    }
    if (i < NN) {
        if (is64) g_batch[i] = (int)((const long long*)bt)[i];
        else      g_batch[i] = ((const int*)bt)[i];
        g_counts[i] = 0;
    }
    if (i < NG)    g_gcnt[i] = 0;
    if (i < OUTSZ) out[i] = 0.0f;
}

__global__ void hist_kernel() {
    int i = blockIdx.x * blockDim.x + threadIdx.x;
    if (i < NE) atomicAdd(&g_counts[g_dst[i]], 1);
    if (i < NN) atomicAdd(&g_gcnt[g_batch[i]], 1);
}

__global__ void scan_block_kernel() {
    __shared__ int sh[1024];
    int t = threadIdx.x;
    int i = blockIdx.x * 1024 + t;
    int v = (i < NN) ? g_counts[i] : 0;
    sh[t] = v;
    __syncthreads();
    for (int off = 1; off < 1024; off <<= 1) {
        int tmp = (t >= off) ? sh[t - off] : 0;
        __syncthreads();
        sh[t] += tmp;
        __syncthreads();
    }
    if (i < NN) g_rowptr[i] = sh[t] - v;
    if (t == 1023) g_bsums[blockIdx.x] = sh[1023];
}

// block 0: serial scan of per-block sums; block 1: scan of graph counts (batch CSR)
__global__ void scan_misc_kernel(int nb) {
    __shared__ int sg[NG];
    int t = threadIdx.x;
    if (blockIdx.x == 0) {
        if (t == 0) {
            int run = 0;
            for (int i = 0; i < nb; i++) { g_boffs[i] = run; run += g_bsums[i]; }
            g_rowptr[NN] = run;
        }
    } else {
        int v = (t < NG) ? g_gcnt[t] : 0;
        if (t < NG) sg[t] = v;
        __syncthreads();
        for (int off = 1; off < NG; off <<= 1) {
            int tmp = (t < NG && t >= off) ? sg[t - off] : 0;
            __syncthreads();
            if (t < NG) sg[t] += tmp;
            __syncthreads();
        }
        if (t < NG) { g_grow[t] = sg[t] - v; g_gcur[t] = sg[t] - v; }
        if (t == NG - 1) g_grow[NG] = sg[NG - 1];
    }
}

__global__ void scan_add_kernel() {
    int i = blockIdx.x * blockDim.x + threadIdx.x;
    if (i < NN) {
        int r = g_rowptr[i] + g_boffs[i >> 10];
        g_rowptr[i] = r;
        g_cursor[i] = r;
    }
}

__global__ void scatter_both_kernel() {
    int i = blockIdx.x * blockDim.x + threadIdx.x;
    if (i < NE) {
        int p = atomicAdd(&g_cursor[g_dst[i]], 1);
        g_col[p] = g_src[i];
    }
    if (i < NN) {
        int p = atomicAdd(&g_gcur[g_batch[i]], 1);
        g_glist[p] = i;
    }
}

// ---------------- weight hi/lo prep (all 6 panels in one kernel) ----------------
__global__ void prep_w_all_kernel(
    const float* __restrict__ w1a, const float* __restrict__ w1b, const float* __restrict__ w1c,
    const float* __restrict__ w2a, const float* __restrict__ w2b, const float* __restrict__ w2c,
    __nv_bfloat16* __restrict__ w1h, __nv_bfloat16* __restrict__ w1l,
    __nv_bfloat16* __restrict__ w2h, __nv_bfloat16* __restrict__ w2l) {
    const int S1 = NC1 * KP1, S2 = NC2 * KP2;
    int i = blockIdx.x * blockDim.x + threadIdx.x;
    if (i < 3 * S1) {
        int c = i / S1, r0 = i - c * S1;
        int r = r0 / KP1, k = r0 - r * KP1;
        const float* w = (c == 0) ? w1a : (c == 1) ? w1b : w1c;
        float v = (r < 200 && k < 100) ? w[r * 100 + k] : 0.f;
        st_hilo(w1h, w1l, i, v);
    } else {
        int j = i - 3 * S1;
        if (j >= 3 * S2) return;
        int c = j / S2, r0 = j - c * S2;
        int r = r0 / KP2, k = r0 - r * KP2;
        const float* w = (c == 0) ? w2a : (c == 1) ? w2b : w2c;
        float v = (r < 100 && k < 200) ? w[r * 200 + k] : 0.f;
        st_hilo(w2h, w2l, j, v);
    }
}

// ---------------- conv1 input linears ----------------
__global__ void lin10_kernel(const float* __restrict__ x,
                             const float* __restrict__ sw_, const float* __restrict__ sb_,
                             const float* __restrict__ dw_, const float* __restrict__ db_,
                             float* __restrict__ m_out, float* __restrict__ xd_out) {
    __shared__ float sw[1000], dw[1000], sb[100], db[100];
    int t = threadIdx.x;
    for (int i = t; i < 1000; i += blockDim.x) { sw[i] = sw_[i]; dw[i] = dw_[i]; }
    for (int i = t; i < 100;  i += blockDim.x) { sb[i] = sb_[i]; db[i] = db_[i]; }
    __syncthreads();
    int id = blockIdx.x * blockDim.x + t;
    if (id >= NN * FD) return;
    int n = id / FD, f = id - n * FD;
    float xs[10];
#pragma unroll
    for (int k = 0; k < 10; k++) xs[k] = x[n * 10 + k];
    float a = sb[f], b = db[f];
#pragma unroll
    for (int k = 0; k < 10; k++) { a += xs[k] * sw[f * 10 + k]; b += xs[k] * dw[f * 10 + k]; }
    m_out[id]  = fmaxf(a, 0.0f) + 1e-7f;
    xd_out[id] = b;
}

// ---------------- softmax aggregation: ONLINE single-pass (1 exp/feature/edge) ----------------
// Warp per dst node; lane l (<25) owns features 4l..4l+3 (one float4 gather per edge).
// Writes GEMM1 operand rows [KP1=112] as bf16 hi/lo: cols 0..99 = num/den + xd, 100..111 = 0.
template<bool TRANS>
__global__ void agg_kernel(const float* __restrict__ m, const float* __restrict__ xd,
                           __nv_bfloat16* __restrict__ oh, __nv_bfloat16* __restrict__ ol) {
    int w = (blockIdx.x * blockDim.x + threadIdx.x) >> 5;
    if (w >= NN) return;
    int lane = threadIdx.x & 31;
    size_t orow = (size_t)w * KP1;

    if (lane < 25) {
        int beg = g_rowptr[w], end = g_rowptr[w + 1];
        float4 mx = make_float4(0.f, 0.f, 0.f, 0.f);
        float4 d  = make_float4(0.f, 0.f, 0.f, 0.f);
        float4 n  = make_float4(0.f, 0.f, 0.f, 0.f);
        int s_next = (beg < end) ? __ldg(&g_col[beg]) : 0;
        for (int i = beg; i < end; i++) {
            int s = s_next;
            if (i + 1 < end) s_next = __ldg(&g_col[i + 1]);   // prefetch next row id
            float4 v = __ldg((const float4*)(m + (size_t)s * FD) + lane);
            if (TRANS) {
                v.x = fmaxf(v.x, 0.f) + 1e-7f; v.y = fmaxf(v.y, 0.f) + 1e-7f;
                v.z = fmaxf(v.z, 0.f) + 1e-7f; v.w = fmaxf(v.w, 0.f) + 1e-7f;
            }
            onl(v.x, mx.x, d.x, n.x);
            onl(v.y, mx.y, d.y, n.y);
            onl(v.z, mx.z, d.z, n.z);
            onl(v.w, mx.w, d.w, n.w);
        }
        float4 xv = __ldg((const float4*)(xd + (size_t)w * FD) + lane);
        float o0 = n.x / (d.x + 1e-16f) + xv.x;
        float o1 = n.y / (d.y + 1e-16f) + xv.y;
        float o2 = n.z / (d.z + 1e-16f) + xv.z;
        float o3 = n.w / (d.w + 1e-16f) + xv.w;
        __nv_bfloat162 h01 = __floats2bfloat162_rn(o0, o1);
        __nv_bfloat162 h23 = __floats2bfloat162_rn(o2, o3);
        uint2 hv, lv;
        hv.x = reinterpret_cast<uint32_t&>(h01);
        hv.y = reinterpret_cast<uint32_t&>(h23);
        lv.x = pack_bf2(o0 - __low2float(h01), o1 - __high2float(h01));
        lv.y = pack_bf2(o2 - __low2float(h23), o3 - __high2float(h23));
        *(uint2*)((char*)oh + (orow + 4 * lane) * 2) = hv;
        *(uint2*)((char*)ol + (orow + 4 * lane) * 2) = lv;
    } else if (lane < 28) {       // zero pad cols 100..111 (4*lane = 100,104,108)
        uint2 z = make_uint2(0u, 0u);
        *(uint2*)((char*)oh + (orow + 4 * lane) * 2) = z;
        *(uint2*)((char*)ol + (orow + 4 * lane) * 2) = z;
    }
}

// ============ persistent mma.sync bf16 GEMM: C[M, NCOV] = A @ W^T ============
// 3 error-compensated passes: AhWh + AhWl + AlWh, fp32 accumulate.
// SMS % 64 == 56 -> conflict-free ldmatrix.
// EPI 0: relu((acc+bias)*gamma*rsqrt(1+1e-5)+beta) -> bf16 hi/lo Oh/Ol [NN,NCOV]
// EPI 1: relu(acc+bias) -> fp32 Of [NN,100]
template<int NOUT, int NCOV, int KPAD, int SMS, int MT, int MF, int NF, int WARPS_M, int EPI>
__global__ __launch_bounds__(256, 1) void mma_gemm_kernel(
    const __nv_bfloat16* __restrict__ Ah, const __nv_bfloat16* __restrict__ Al,
    const __nv_bfloat16* __restrict__ Wh, const __nv_bfloat16* __restrict__ Wl,
    const float* __restrict__ bias, const float* __restrict__ gamma, const float* __restrict__ beta,
    __nv_bfloat16* __restrict__ Oh, __nv_bfloat16* __restrict__ Ol, float* __restrict__ Of) {

    constexpr int WM = MF * 16;
    constexpr int WN = NF * 8;
    constexpr int KC = KPAD / 8;
    constexpr int KS = KPAD / 16;
    constexpr int POFF = (3 * NCOV * 4 + 15) & ~15;

    extern __shared__ char sm[];
    float* p_b = (float*)sm;
    float* p_s = p_b + NCOV;
    float* p_e = p_s + NCOV;
    __nv_bfloat16* sAh = (__nv_bfloat16*)(sm + POFF);
    __nv_bfloat16* sAl = sAh + MT * SMS;
    __nv_bfloat16* sWh = sAl + MT * SMS;
    __nv_bfloat16* sWl = sWh + NCOV * SMS;

    const int tid = threadIdx.x, wid = tid >> 5, lane = tid & 31;
    const int wm = wid % WARPS_M, wn = wid / WARPS_M;

    const float rs = rsqrtf(1.0f + 1e-5f);
    for (int i = tid; i < NCOV; i += 256) {
        p_b[i] = (i < NOUT) ? bias[i] : 0.f;
        if (EPI == 0) {
            p_s[i] = (i < NOUT) ? gamma[i] * rs : 0.f;
            p_e[i] = (i < NOUT) ? beta[i] : 0.f;
        }
    }
    for (int u = tid; u < NCOV * KC; u += 256) {
        int r = u / KC, k8 = u - r * KC;
        size_t gi = (size_t)r * KPAD + k8 * 8;
        *(uint4*)(sWh + r * SMS + k8 * 8) = *(const uint4*)(Wh + gi);
        *(uint4*)(sWl + r * SMS + k8 * 8) = *(const uint4*)(Wl + gi);
    }
    __syncthreads();

    const uint32_t uAh = smem_u32(sAh), uAl = smem_u32(sAl);
    const uint32_t uWh = smem_u32(sWh), uWl = smem_u32(sWl);
    const int a_row  = wm * WM + (lane & 15);
    const int a_koff = (lane >> 4) * 8;
    const int b_row  = wn * WN + (lane & 7);
    const int b_koff = ((lane >> 3) & 1) * 8;

    const int NT = (NN + MT - 1) / MT;
    for (int tile = blockIdx.x; tile < NT; tile += gridDim.x) {
        const int row0 = tile * MT;
        for (int u = tid; u < MT * KC; u += 256) {
            int r = u / KC, k8 = u - r * KC;
            int gr = row0 + r;
            uint4 vh = make_uint4(0, 0, 0, 0), vl = make_uint4(0, 0, 0, 0);
            if (gr < NN) {
                size_t gi = (size_t)gr * KPAD + k8 * 8;
                vh = *(const uint4*)(Ah + gi);
                vl = *(const uint4*)(Al + gi);
            }
            *(uint4*)(sAh + r * SMS + k8 * 8) = vh;
            *(uint4*)(sAl + r * SMS + k8 * 8) = vl;
        }
        __syncthreads();

        float acc[MF][NF][4];
#pragma unroll
        for (int m = 0; m < MF; m++)
#pragma unroll
            for (int nf = 0; nf < NF; nf++)
#pragma unroll
                for (int j = 0; j < 4; j++) acc[m][nf][j] = 0.f;

#pragma unroll 1
        for (int pass = 0; pass < 3; pass++) {
            const uint32_t uA = (pass == 2) ? uAl : uAh;
            const uint32_t uW = (pass == 1) ? uWl : uWh;
#pragma unroll 1
            for (int ks = 0; ks < KS; ks++) {
                uint32_t af[MF][4];
#pragma unroll
                for (int m = 0; m < MF; m++)
                    ldmx4(af[m], uA + (uint32_t)(((a_row + m * 16) * SMS + ks * 16 + a_koff) * 2));
                uint32_t bf[NF][2];
#pragma unroll
                for (int nf = 0; nf < NF; nf++)
                    ldmx2(bf[nf], uW + (uint32_t)(((b_row + nf * 8) * SMS + ks * 16 + b_koff) * 2));
#pragma unroll
                for (int m = 0; m < MF; m++)
#pragma unroll
                    for (int nf = 0; nf < NF; nf++)
                        mma16816(acc[m][nf], af[m], bf[nf]);
            }
        }

#pragma unroll
        for (int m = 0; m < MF; m++) {
            int r0 = row0 + wm * WM + m * 16 + (lane >> 2);
#pragma unroll
            for (int nf = 0; nf < NF; nf++) {
                int c0 = wn * WN + nf * 8 + (lane & 3) * 2;
#pragma unroll
                for (int h = 0; h < 2; h++) {
                    int r = r0 + h * 8;
                    if (r >= NN) continue;
                    float d0 = acc[m][nf][2 * h], d1 = acc[m][nf][2 * h + 1];
                    if (EPI == 0) {
                        float v0 = 0.f, v1 = 0.f;
                        if (c0 < NOUT) {
                            v0 = fmaxf((d0 + p_b[c0])     * p_s[c0]     + p_e[c0],     0.f);
                            v1 = fmaxf((d1 + p_b[c0 + 1]) * p_s[c0 + 1] + p_e[c0 + 1], 0.f);
                        }
                        __nv_bfloat162 h2 = __floats2bfloat162_rn(v0, v1);
                        uint32_t uh = reinterpret_cast<uint32_t&>(h2);
                        uint32_t ul = pack_bf2(v0 - __low2float(h2), v1 - __high2float(h2));
                        *(uint32_t*)((char*)Oh + ((size_t)r * NCOV + c0) * 2) = uh;
                        *(uint32_t*)((char*)Ol + ((size_t)r * NCOV + c0) * 2) = ul;
                    } else {
                        if (c0 < NOUT) {
                            float2 y;
                            y.x = fmaxf(d0 + p_b[c0],     0.f);
                            y.y = fmaxf(d1 + p_b[c0 + 1], 0.f);
                            *(float2*)(Of + (size_t)r * 100 + c0) = y;
                        }
                    }
                }
            }
        }
        __syncthreads();
    }
}

// ---------------- readout: block per graph, atomic-free segment sum/max ----------------
__global__ void readout_seg_kernel(const float* __restrict__ h, float* __restrict__ encode) {
    int g = blockIdx.x, t = threadIdx.x;
    if (t >= 100) return;
    int beg = g_grow[g], end = g_grow[g + 1];
    float s = 0.f, mx = 0.f;
    int i = beg;
    for (; i + 3 < end; i += 4) {
        int n0 = g_glist[i], n1 = g_glist[i + 1], n2 = g_glist[i + 2], n3 = g_glist[i + 3];
        float v0 = __ldg(&h[(size_t)n0 * FD + t]);
        float v1 = __ldg(&h[(size_t)n1 * FD + t]);
        float v2 = __ldg(&h[(size_t)n2 * FD + t]);
        float v3 = __ldg(&h[(size_t)n3 * FD + t]);
        s += v0 + v1 + v2 + v3;
        mx = fmaxf(mx, fmaxf(fmaxf(v0, v1), fmaxf(v2, v3)));
    }
    for (; i < end; i++) {
        float v = __ldg(&h[(size_t)g_glist[i] * FD + t]);
        s += v; mx = fmaxf(mx, v);
    }
    float cnt = (float)(end - beg);
    float mean = s / fmaxf(cnt, 1.0f);
    encode[g * FD2 + t]      += fmaxf(mean, 0.f);
    encode[g * FD2 + FD + t] += fmaxf(mx,   0.f);
}

// ---------------- head ----------------
__global__ void head_kernel(const float* __restrict__ encode,
                            const float* __restrict__ fc1_w, const float* __restrict__ fc1_b,
                            const float* __restrict__ cls_w, const float* __restrict__ cls_b,
                            float* __restrict__ logits) {
    __shared__ float enc[200];
    __shared__ float z[100];
    int g = blockIdx.x, t = threadIdx.x;
    for (int i = t; i < 200; i += 128) enc[i] = encode[g * 200 + i];
    __syncthreads();
    if (t < 100) {
        float a = fc1_b[t];
#pragma unroll 4
        for (int k = 0; k < 200; k++) a += enc[k] * __ldg(&fc1_w[t * 200 + k]);
        z[t] = fmaxf(a, 0.f);
    }
    __syncthreads();
    if (t < 64) {
        int o = t >> 5, lane = t & 31;
        float s = 0.f;
        for (int j = lane; j < 100; j += 32) s += z[j] * __ldg(&cls_w[o * 100 + j]);
#pragma unroll
        for (int off = 16; off; off >>= 1) s += __shfl_down_sync(0xffffffffu, s, off);
        if (lane == 0) logits[g * 2 + o] = s + cls_b[o];
    }
}

// ---------------- launch ----------------
extern "C" void kernel_launch(void* const* d_in, const int* in_sizes, int n_in,
                              void* d_out, int out_size) {
    const float* x       = (const float*)d_in[0];
    const void*  ei      = d_in[1];
    const void*  bt      = d_in[2];
    const float* c1_src_w = (const float*)d_in[3];
    const float* c1_src_b = (const float*)d_in[4];
    const float* c1_dst_w = (const float*)d_in[5];
    const float* c1_dst_b = (const float*)d_in[6];
    const float* cw1[3] = { (const float*)d_in[7],  (const float*)d_in[13], (const float*)d_in[19] };
    const float* cb1[3] = { (const float*)d_in[8],  (const float*)d_in[14], (const float*)d_in[20] };
    const float* cg [3] = { (const float*)d_in[9],  (const float*)d_in[15], (const float*)d_in[21] };
    const float* cbe[3] = { (const float*)d_in[10], (const float*)d_in[16], (const float*)d_in[22] };
    const float* cw2[3] = { (const float*)d_in[11], (const float*)d_in[17], (const float*)d_in[23] };
    const float* cb2[3] = { (const float*)d_in[12], (const float*)d_in[18], (const float*)d_in[24] };
    const float* fc1_w = (const float*)d_in[25];
    const float* fc1_b = (const float*)d_in[26];
    const float* cls_w = (const float*)d_in[27];
    const float* cls_b = (const float*)d_in[28];

    float* out    = (float*)d_out;
    float* logits = out;
    float* encode = out + NG * 2;

    float *pm, *pxd, *ph;
    cudaGetSymbolAddress((void**)&pm,   g_m);
    cudaGetSymbolAddress((void**)&pxd,  g_xd);
    cudaGetSymbolAddress((void**)&ph,   g_h);
    __nv_bfloat16 *pa1h, *pa1l, *pa2h, *pa2l, *pw1h, *pw1l, *pw2h, *pw2l;
    cudaGetSymbolAddress((void**)&pa1h, g_a1h);
    cudaGetSymbolAddress((void**)&pa1l, g_a1l);
    cudaGetSymbolAddress((void**)&pa2h, g_a2h);
    cudaGetSymbolAddress((void**)&pa2l, g_a2l);
    cudaGetSymbolAddress((void**)&pw1h, g_w1h);
    cudaGetSymbolAddress((void**)&pw1l, g_w1l);
    cudaGetSymbolAddress((void**)&pw2h, g_w2h);
    cudaGetSymbolAddress((void**)&pw2l, g_w2l);

    // GEMM1: <200,208,112,120,128,2,13,4,0>  GEMM2: <100,112,208,248,64,1,7,4,1>
    const int SM1 = ((3 * NC1 * 4 + 15) & ~15) + 2 * 128 * 120 * 2 + 2 * NC1 * 120 * 2;
    const int SM2 = ((3 * NC2 * 4 + 15) & ~15) + 2 * 64 * 248 * 2 + 2 * NC2 * 248 * 2;
    cudaFuncSetAttribute(mma_gemm_kernel<200, NC1, KP1, 120, 128, 2, 13, 4, 0>,
                         cudaFuncAttributeMaxDynamicSharedMemorySize, SM1);
    cudaFuncSetAttribute(mma_gemm_kernel<100, NC2, KP2, 248, 64, 1, 7, 4, 1>,
                         cudaFuncAttributeMaxDynamicSharedMemorySize, SM2);

    const int TB = 256;
    const int GE  = (NE + TB - 1) / TB;
    const int GNF = (NN * FD + TB - 1) / TB;
    const int NB_SCAN = (NN + 1023) / 1024;
    const int GEMM_GRID = 148;
    const int WTOT = 3 * (NC1 * KP1 + NC2 * KP2);

    // CSR build (dst identical across convs -> build once) + batch CSR for readout
    detect_kernel<<<1, 1024>>>((const unsigned long long*)ei);
    prep_kernel<<<GE, TB>>>(ei, bt, out);
    hist_kernel<<<GE, TB>>>();
    scan_block_kernel<<<NB_SCAN, 1024>>>();
    scan_misc_kernel<<<2, 1024>>>(NB_SCAN);
    scan_add_kernel<<<(NN + TB - 1) / TB, TB>>>();
    scatter_both_kernel<<<GE, TB>>>();
    prep_w_all_kernel<<<(WTOT + TB - 1) / TB, TB>>>(cw1[0], cw1[1], cw1[2],
                                                    cw2[0], cw2[1], cw2[2],
                                                    pw1h, pw1l, pw2h, pw2l);

    // ---- conv1 ----
    lin10_kernel<<<GNF, TB>>>(x, c1_src_w, c1_src_b, c1_dst_w, c1_dst_b, pm, pxd);
    agg_kernel<false><<<(NN * 32 + TB - 1) / TB, TB>>>(pm, pxd, pa1h, pa1l);
    mma_gemm_kernel<200, NC1, KP1, 120, 128, 2, 13, 4, 0><<<GEMM_GRID, 256, SM1>>>(
        pa1h, pa1l, pw1h, pw1l, cb1[0], cg[0], cbe[0], pa2h, pa2l, nullptr);
    mma_gemm_kernel<100, NC2, KP2, 248, 64, 1, 7, 4, 1><<<GEMM_GRID, 256, SM2>>>(
        pa2h, pa2l, pw2h, pw2l, cb2[0], nullptr, nullptr, nullptr, nullptr, ph);
    readout_seg_kernel<<<NG, 128>>>(ph, encode);

    // ---- conv2 / conv3 ----
    for (int c = 1; c < 3; c++) {
        agg_kernel<true><<<(NN * 32 + TB - 1) / TB, TB>>>(ph, ph, pa1h, pa1l);
        mma_gemm_kernel<200, NC1, KP1, 120, 128, 2, 13, 4, 0><<<GEMM_GRID, 256, SM1>>>(
            pa1h, pa1l, pw1h + c * NC1 * KP1, pw1l + c * NC1 * KP1,
            cb1[c], cg[c], cbe[c], pa2h, pa2l, nullptr);
        mma_gemm_kernel<100, NC2, KP2, 248, 64, 1, 7, 4, 1><<<GEMM_GRID, 256, SM2>>>(
            pa2h, pa2l, pw2h + c * NC2 * KP2, pw2l + c * NC2 * KP2,
            cb2[c], nullptr, nullptr, nullptr, nullptr, ph);
        readout_seg_kernel<<<NG, 128>>>(ph, encode);
    }

    head_kernel<<<NG, 128>>>(encode, fc1_w, fc1_b, cls_w, cls_b, logits);
}